// round 13
// baseline (speedup 1.0000x reference)
#include <cuda_runtime.h>
#include <cuda_fp16.h>
#include <math.h>
#include <stdint.h>

#define TN 9216
#define NB 2
typedef unsigned int u32;
typedef unsigned long long u64;

#define F_RELU   1
#define F_BROW   2
#define F_BCOL   4
#define F_F32    16

// ---------------- scratch (static device arrays; no cudaMalloc allowed) ----
__device__ __half g_xh[(size_t)NB*TN*512];
__device__ __half g_kh[(size_t)NB*TN*512];
__device__ __half g_vh[(size_t)NB*256*TN];
__device__ float  g_att[(size_t)NB*TN*TN];      // 680 MB fp32 sim
__device__ __half g_ch[(size_t)NB*TN*256];
__device__ __half g_c2h[(size_t)NB*TN*512];
__device__ __half g_wkh[512*512];
__device__ __half g_wvh[256*512];
__device__ __half g_wWh[512*256];
__device__ __half g_woh[512*512];
__device__ float g_bkf[512], g_bof[512];
__device__ u32   g_rmax[NB*TN];

// ---------------- helpers ----------------------------------------------------
static __device__ __forceinline__ u32 smem_u32(const void* p){
    u32 a;
    asm("{ .reg .u64 t; cvta.to.shared.u64 t, %1; cvt.u32.u64 %0, t; }" : "=r"(a) : "l"(p));
    return a;
}
static __device__ __forceinline__ void cpasync16(u32 s, const void* g){
    asm volatile("cp.async.cg.shared.global [%0], [%1], 16;" :: "r"(s), "l"(g) : "memory");
}
#define CP_COMMIT() asm volatile("cp.async.commit_group;" ::: "memory")
#define CP_WAIT0()  asm volatile("cp.async.wait_group 0;" ::: "memory")
#define CP_WAIT1()  asm volatile("cp.async.wait_group 1;" ::: "memory")

static __device__ __forceinline__ void ldsm4(u32& r0, u32& r1, u32& r2, u32& r3, u32 a){
    asm volatile("ldmatrix.sync.aligned.m8n8.x4.shared.b16 {%0,%1,%2,%3}, [%4];"
                 : "=r"(r0), "=r"(r1), "=r"(r2), "=r"(r3) : "r"(a));
}
static __device__ __forceinline__ void mma16816(float* d, const u32* a, const u32* b){
    asm volatile("mma.sync.aligned.m16n8k16.row.col.f32.f16.f16.f32 "
                 "{%0,%1,%2,%3}, {%4,%5,%6,%7}, {%8,%9}, {%0,%1,%2,%3};"
                 : "+f"(d[0]), "+f"(d[1]), "+f"(d[2]), "+f"(d[3])
                 : "r"(a[0]), "r"(a[1]), "r"(a[2]), "r"(a[3]), "r"(b[0]), "r"(b[1]));
}
static __device__ __forceinline__ u32 fenc(float f){
    u32 u = __float_as_uint(f);
    return (u & 0x80000000u) ? ~u : (u | 0x80000000u);
}
static __device__ __forceinline__ float fdec(u32 u){
    return (u & 0x80000000u) ? __uint_as_float(u ^ 0x80000000u) : __uint_as_float(~u);
}

// ---------------- single-pass fp16 tensor GEMM (3-stage, 2 CTAs/SM) ----------
__global__ void __launch_bounds__(256,2) gemm_tc(
    const __half* __restrict__ a, size_t a_bs, int lda,
    const __half* __restrict__ b, size_t b_bs, int ldb,
    int K, int flags, const float* __restrict__ bias,
    __half* oh, float* of, size_t o_bs, int ldo)
{
    extern __shared__ char dsm[];
    const int tid = threadIdx.x, wid = tid>>5, lid = tid&31;
    const int m0 = blockIdx.x*128, n0 = blockIdx.y*128, z = blockIdx.z;
    a += (size_t)z*a_bs; b += (size_t)z*b_bs;
    const int wm = wid>>2, wn = wid&3;
    const u32 sb = smem_u32(dsm);
    const int lrow = tid>>3, lc = tid&7;

    float acc[4][4][4];
#pragma unroll
    for (int i=0;i<4;i++)
#pragma unroll
        for (int j=0;j<4;j++)
#pragma unroll
            for (int q=0;q<4;q++) acc[i][j][q] = 0.f;

    const int S = K >> 6;
    auto issue = [&](int s){
        const int k0 = s << 6;
        const u32 bufo = (u32)(s % 3) * 32768u;
#pragma unroll
        for (int arr=0; arr<2; arr++){
            const __half* gp = arr ? b : a;
            const int rb = arr ? n0 : m0;
            const int ld = arr ? ldb : lda;
            const u32 so = sb + bufo + arr*16384u;
#pragma unroll
            for (int i=0;i<4;i++){
                const int row = lrow + i*32;
                const void* g = gp + (size_t)(rb+row)*ld + k0 + lc*8;
                const u32 sa = so + (u32)(row*128) + (u32)((lc ^ (row&7)) << 4);
                cpasync16(sa, g);
            }
        }
        CP_COMMIT();
    };

    issue(0);
    issue(1);
    for (int s=0; s<S; s++){
        if (s+1 < S) { CP_WAIT1(); } else { CP_WAIT0(); }
        __syncthreads();
        if (s+2 < S) issue(s+2);
        const u32 bufo = (u32)(s % 3) * 32768u;
        const u32 bA = sb+bufo, bB = sb+bufo+16384u;
        const int prA = (wm*64 + (lid&15)) * 128;
        const int prB0 = (wn*32 +      (lid&7) + ((lid>>4)<<3)) * 128;
        const int prB1 = (wn*32 + 16 + (lid&7) + ((lid>>4)<<3)) * 128;
#pragma unroll
        for (int st=0; st<4; st++){
            u32 Ah[4][4], Bh[4][2];
            const int xa = ((st*2 + (lid>>4))    ^ (lid&7)) << 4;
            const int xb = ((st*2 + ((lid>>3)&1)) ^ (lid&7)) << 4;
#pragma unroll
            for (int i=0;i<4;i++)
                ldsm4(Ah[i][0],Ah[i][1],Ah[i][2],Ah[i][3], bA + prA + i*2048 + xa);
            {
                u32 r0,r1,r2,r3;
                ldsm4(r0,r1,r2,r3, bB + prB0 + xb);
                Bh[0][0]=r0; Bh[0][1]=r1; Bh[1][0]=r2; Bh[1][1]=r3;
                ldsm4(r0,r1,r2,r3, bB + prB1 + xb);
                Bh[2][0]=r0; Bh[2][1]=r1; Bh[3][0]=r2; Bh[3][1]=r3;
            }
#pragma unroll
            for (int i=0;i<4;i++)
#pragma unroll
                for (int j=0;j<4;j++) mma16816(acc[i][j], Ah[i], Bh[j]);
        }
    }

    const int tr = lid>>2, tc = (lid&3)*2;
    const int mBase = m0 + wm*64, nBase = n0 + wn*32;
#pragma unroll
    for (int i=0;i<4;i++){
#pragma unroll
        for (int hh=0; hh<2; hh++){
            const int row = mBase + i*16 + tr + hh*8;
            float brow = (flags & F_BROW) ? bias[row] : 0.f;
            if (flags & F_F32){
                float* op = of + (size_t)z*o_bs + (size_t)row*ldo;
#pragma unroll
                for (int j=0;j<4;j++){
                    const int n = nBase + j*8 + tc;
                    float v0 = acc[i][j][hh*2+0] + brow;
                    float v1 = acc[i][j][hh*2+1] + brow;
                    if (flags & F_BCOL){ v0 += bias[n]; v1 += bias[n+1]; }
                    if (flags & F_RELU){ v0 = fmaxf(v0,0.f); v1 = fmaxf(v1,0.f); }
                    float2 w; w.x = v0; w.y = v1;
                    *(float2*)(op + n) = w;
                }
            } else {
                __half* oph = oh + (size_t)z*o_bs + (size_t)row*ldo;
#pragma unroll
                for (int j=0;j<4;j++){
                    const int n = nBase + j*8 + tc;
                    float v0 = acc[i][j][hh*2+0] + brow;
                    float v1 = acc[i][j][hh*2+1] + brow;
                    if (flags & F_BCOL){ v0 += bias[n]; v1 += bias[n+1]; }
                    if (flags & F_RELU){ v0 = fmaxf(v0,0.f); v1 = fmaxf(v1,0.f); }
                    *(__half2*)(oph + n) = __floats2half2_rn(v0, v1);
                }
            }
        }
    }
}

// ---------------- symmetric sim GEMM: fp16 1-pass, fp32 out, 3-stage ---------
__global__ void __launch_bounds__(256,2) gemm_sym(
    const __half* __restrict__ kh,
    float scale, float* __restrict__ att, u32* __restrict__ rmaxU)
{
    extern __shared__ char dsm[];
    const int tid = threadIdx.x, wid = tid>>5, lid = tid&31;
    const int z = blockIdx.z;
    const int t = blockIdx.x;
    int i = (int)((145.0f - sqrtf(21025.0f - 8.0f*(float)t)) * 0.5f);
    while (i > 0 && i*72 - i*(i-1)/2 > t) i--;
    while ((i+1)*72 - (i+1)*i/2 <= t) i++;
    const int j = i + (t - (i*72 - i*(i-1)/2));
    const int m0 = i*128, n0 = j*128;

    const __half* ah = kh + (size_t)z*TN*512;
    const int wm = wid>>2, wn = wid&3;
    const u32 sb = smem_u32(dsm);
    const int lrow = tid>>3, lc = tid&7;

    float acc[4][4][4];
#pragma unroll
    for (int a=0;a<4;a++)
#pragma unroll
        for (int b=0;b<4;b++)
#pragma unroll
            for (int q=0;q<4;q++) acc[a][b][q] = 0.f;

    auto issue = [&](int s){
        const int k0 = s << 6;
        const u32 bufo = (u32)(s % 3) * 32768u;
#pragma unroll
        for (int arr=0; arr<2; arr++){
            const int rb = arr ? n0 : m0;
            const u32 so = sb + bufo + arr*16384u;
#pragma unroll
            for (int q=0;q<4;q++){
                const int row = lrow + q*32;
                const void* g = ah + (size_t)(rb+row)*512 + k0 + lc*8;
                const u32 sa = so + (u32)(row*128) + (u32)((lc ^ (row&7)) << 4);
                cpasync16(sa, g);
            }
        }
        CP_COMMIT();
    };

    issue(0); issue(1);
    for (int s=0; s<8; s++){
        if (s+1 < 8) { CP_WAIT1(); } else { CP_WAIT0(); }
        __syncthreads();
        if (s+2 < 8) issue(s+2);
        const u32 bufo = (u32)(s % 3) * 32768u;
        const u32 bA = sb+bufo, bB = sb+bufo+16384u;
        const int prA = (wm*64 + (lid&15)) * 128;
        const int prB0 = (wn*32 +      (lid&7) + ((lid>>4)<<3)) * 128;
        const int prB1 = (wn*32 + 16 + (lid&7) + ((lid>>4)<<3)) * 128;
#pragma unroll
        for (int st=0; st<4; st++){
            u32 Ah[4][4], Bh[4][2];
            const int xa = ((st*2 + (lid>>4))    ^ (lid&7)) << 4;
            const int xb = ((st*2 + ((lid>>3)&1)) ^ (lid&7)) << 4;
#pragma unroll
            for (int a=0;a<4;a++)
                ldsm4(Ah[a][0],Ah[a][1],Ah[a][2],Ah[a][3], bA + prA + a*2048 + xa);
            {
                u32 r0,r1,r2,r3;
                ldsm4(r0,r1,r2,r3, bB + prB0 + xb);
                Bh[0][0]=r0; Bh[0][1]=r1; Bh[1][0]=r2; Bh[1][1]=r3;
                ldsm4(r0,r1,r2,r3, bB + prB1 + xb);
                Bh[2][0]=r0; Bh[2][1]=r1; Bh[3][0]=r2; Bh[3][1]=r3;
            }
#pragma unroll
            for (int a=0;a<4;a++)
#pragma unroll
                for (int b=0;b<4;b++) mma16816(acc[a][b], Ah[a], Bh[b]);
        }
    }

    // stage scaled fp32 tile (stride 129 floats — scalar LDS only!)
    __syncthreads();
    float* Sm = (float*)dsm;
    float* P  = Sm + 128*129;
    const int tr = lid>>2, tc = (lid&3)*2;
#pragma unroll
    for (int a=0;a<4;a++)
#pragma unroll
        for (int hh=0; hh<2; hh++){
            const int rl = wm*64 + a*16 + tr + hh*8;
#pragma unroll
            for (int b=0;b<4;b++){
                const int cl = wn*32 + b*8 + tc;
                Sm[rl*129 + cl]     = acc[a][b][hh*2+0]*scale;
                Sm[rl*129 + cl + 1] = acc[a][b][hh*2+1]*scale;
            }
        }
    __syncthreads();

    const int rr = tid & 127, hf2 = tid >> 7;
    {
        float m = -1e30f;
        for (int c=0;c<64;c++) m = fmaxf(m, Sm[rr*129 + hf2*64 + c]);
        P[rr*2 + hf2] = m;
    }
    __syncthreads();
    if (tid < 128) atomicMax(&rmaxU[(size_t)z*TN + m0 + tid], fenc(fmaxf(P[tid*2], P[tid*2+1])));
    __syncthreads();
    {
        float m = -1e30f;
        for (int r2=0;r2<64;r2++) m = fmaxf(m, Sm[(hf2*64 + r2)*129 + rr]);
        P[rr*2 + hf2] = m;
    }
    __syncthreads();
    if (tid < 128) atomicMax(&rmaxU[(size_t)z*TN + n0 + tid], fenc(fmaxf(P[tid*2], P[tid*2+1])));

    const size_t obase = (size_t)z*TN*TN;
    {
        const int r = tid>>1, c0 = (tid&1)*64;
        float* op = att + obase + (size_t)(m0 + r)*TN + n0 + c0;
        const float* Sr = Sm + r*129 + c0;
#pragma unroll
        for (int it=0; it<16; it++){
            float4 w;
            w.x = Sr[it*4 + 0];
            w.y = Sr[it*4 + 1];
            w.z = Sr[it*4 + 2];
            w.w = Sr[it*4 + 3];
            *(float4*)(op + it*4) = w;
        }
    }
    if (i != j){
        const int c = tid>>1, r0 = (tid&1)*64;
        float* op = att + obase + (size_t)(n0 + c)*TN + m0 + r0;
#pragma unroll
        for (int it=0; it<16; it++){
            float4 w;
            w.x = Sm[(r0 + it*4 + 0)*129 + c];
            w.y = Sm[(r0 + it*4 + 1)*129 + c];
            w.z = Sm[(r0 + it*4 + 2)*129 + c];
            w.w = Sm[(r0 + it*4 + 3)*129 + c];
            *(float4*)(op + it*4) = w;
        }
    }
}

// ---------------- fused exp/rowsum/normalize ctx GEMM (512 thr, 16 warps) ----
// M-tile 64, N=256, K=TN. Stage (40960 B): A 8K | B 32K, 3 stages.
// Warp grid 2(m)x8(n), warp tile 32x32. One att row per thread on the A path.
#define CTX_STAGE 40960u
__global__ void __launch_bounds__(512,1) gemm_ctx_fused(
    const float* __restrict__ att,
    const __half* __restrict__ vh,
    const u32* __restrict__ rmaxU,
    __half* __restrict__ ch)
{
    extern __shared__ char dsm[];
    const int tid = threadIdx.x, wid = tid>>5, lid = tid&31;
    const int z = blockIdx.z;
    const int n0 = blockIdx.x*64;
    const size_t abase = (size_t)z*TN*TN;
    const __half* vhb = vh + (size_t)z*256*TN;
    const u32 sb = smem_u32(dsm);
    float* srow = (float*)(dsm + 3*CTX_STAGE);

    const int wm = wid>>3, wn = wid&7;           // 2(m) x 8(n)
    const int lr = tid>>3, lc = tid&7;           // lr in 0..63: one att row each

    const float mx = fdec(rmaxU[(size_t)z*TN + n0 + lr]);
    const float* pA = att + abase + (size_t)(n0+lr)*TN + lc*8;

    float acc[2][4][4];
#pragma unroll
    for (int i=0;i<2;i++)
#pragma unroll
        for (int j=0;j<4;j++)
#pragma unroll
            for (int q=0;q<4;q++) acc[i][j][q] = 0.f;
    float s0 = 0.f;

    const int S = TN/64;   // 144
    __align__(16) float raf[8];
    auto ldgA = [&](int s){
        const int k0 = s<<6;
        *(uint4*)&raf[0] = *(const uint4*)(pA + k0);
        *(uint4*)&raf[4] = *(const uint4*)(pA + k0 + 4);
    };
    auto issueB = [&](int s){
        const int k0 = s<<6;
        const u32 so = sb + (u32)(s%3)*CTX_STAGE + 8192u;
#pragma unroll
        for (int i=0;i<4;i++){
            const int row = lr + i*64;
            cpasync16(so + (u32)(row*128) + (u32)((lc ^ (row&7)) << 4),
                      vhb + (size_t)row*TN + k0 + lc*8);
        }
        CP_COMMIT();
    };
    auto exp8h = [&](const float* f, float mxv, float& ssum)->uint4{
        uint4 r;
        float e0, e1;
        e0 = __expf(f[0] - mxv); e1 = __expf(f[1] - mxv); ssum += e0 + e1;
        { __half2 h = __floats2half2_rn(e0, e1); r.x = *(u32*)&h; }
        e0 = __expf(f[2] - mxv); e1 = __expf(f[3] - mxv); ssum += e0 + e1;
        { __half2 h = __floats2half2_rn(e0, e1); r.y = *(u32*)&h; }
        e0 = __expf(f[4] - mxv); e1 = __expf(f[5] - mxv); ssum += e0 + e1;
        { __half2 h = __floats2half2_rn(e0, e1); r.z = *(u32*)&h; }
        e0 = __expf(f[6] - mxv); e1 = __expf(f[7] - mxv); ssum += e0 + e1;
        { __half2 h = __floats2half2_rn(e0, e1); r.w = *(u32*)&h; }
        return r;
    };
    const int aoff = lr*128 + ((lc ^ (lr&7)) << 4);

    ldgA(0);
    *(uint4*)(dsm + aoff) = exp8h(raf, mx, s0);
    issueB(0);
    issueB(1);

    for (int s=0; s<S; s++){
        if (s+1 < S) ldgA(s+1);
        if (s+1 < S) { CP_WAIT1(); } else { CP_WAIT0(); }
        __syncthreads();
        if (s+2 < S) issueB(s+2);

        const u32 bufo = (u32)(s%3)*CTX_STAGE;
        const u32 bA = sb + bufo, bB = sb + bufo + 8192u;
#pragma unroll
        for (int st=0; st<4; st++){
            u32 Ah[2][4], Bh[4][2];
            const int xa = ((st*2 + (lid>>4))    ^ (lid&7)) << 4;
            const int xb = ((st*2 + ((lid>>3)&1)) ^ (lid&7)) << 4;
#pragma unroll
            for (int i=0;i<2;i++){
                const u32 pr = (u32)((wm*32 + i*16 + (lid&15)) * 128);
                ldsm4(Ah[i][0],Ah[i][1],Ah[i][2],Ah[i][3], bA + pr + xa);
            }
#pragma unroll
            for (int j2=0; j2<2; j2++){
                const u32 pr = (u32)((wn*32 + j2*16 + (lid&7) + ((lid>>4)<<3)) * 128);
                u32 r0,r1,r2,r3;
                ldsm4(r0,r1,r2,r3, bB + pr + xb);
                Bh[2*j2][0]=r0; Bh[2*j2][1]=r1; Bh[2*j2+1][0]=r2; Bh[2*j2+1][1]=r3;
            }
#pragma unroll
            for (int i=0;i<2;i++)
#pragma unroll
                for (int j=0;j<4;j++) mma16816(acc[i][j], Ah[i], Bh[j]);
        }

        if (s+1 < S){
            const int off2 = (int)((u32)((s+1)%3)*CTX_STAGE) + aoff;
            *(uint4*)(dsm + off2) = exp8h(raf, mx, s0);
        }
    }

    // rowsum: reduce over the 8 lanes sharing each row
#pragma unroll
    for (int o=1;o<8;o<<=1)
        s0 += __shfl_xor_sync(0xffffffffu, s0, o);
    __syncthreads();
    if ((tid&7)==0) srow[lr] = s0;
    __syncthreads();

    const int tr = lid>>2, tc2 = (lid&3)*2;
#pragma unroll
    for (int i=0;i<2;i++){
#pragma unroll
        for (int hh=0; hh<2; hh++){
            const int rowl = wm*32 + i*16 + tr + hh*8;
            const float inv = 1.0f / srow[rowl];
            const int row = n0 + rowl;
            __half* oph = ch + (size_t)z*TN*256 + (size_t)row*256 + wn*32;
#pragma unroll
            for (int j=0;j<4;j++){
                const int col = j*8 + tc2;
                *(__half2*)(oph + col) =
                    __floats2half2_rn(acc[i][j][hh*2+0]*inv, acc[i][j][hh*2+1]*inv);
            }
        }
    }
}

// ---------------- merged prep (single fp16 weights) --------------------------
__global__ void prep_all(
    const float* __restrict__ wk, const float* __restrict__ bk,
    const float* __restrict__ g1, const float* __restrict__ b1,
    const float* __restrict__ m1, const float* __restrict__ v1,
    const float* __restrict__ wv,
    const float* __restrict__ wW,
    const float* __restrict__ wo, const float* __restrict__ bo,
    const float* __restrict__ g2, const float* __restrict__ b2,
    const float* __restrict__ m2, const float* __restrict__ v2,
    __half* __restrict__ wkh, float* __restrict__ bkf,
    __half* __restrict__ wvh,
    __half* __restrict__ wWh,
    __half* __restrict__ woh, float* __restrict__ bof)
{
    const int o = blockIdx.x, which = blockIdx.y;
    if (which == 0){
        float s = g1[o] * rsqrtf(v1[o] + 1e-5f);
        for (int c = threadIdx.x; c < 512; c += blockDim.x)
            wkh[o*512 + c] = __float2half_rn(wk[o*512 + c] * s);
        if (threadIdx.x == 0) bkf[o] = bk[o]*s + b1[o] - m1[o]*s;
    } else if (which == 1){
        if (o < 256)
            for (int c = threadIdx.x; c < 512; c += blockDim.x)
                wvh[o*512 + c] = __float2half_rn(wv[o*512 + c]);
    } else if (which == 2){
        for (int c = threadIdx.x; c < 256; c += blockDim.x)
            wWh[o*256 + c] = __float2half_rn(wW[o*256 + c]);
    } else {
        float s = g2[o] * rsqrtf(v2[o] + 1e-5f);
        for (int c = threadIdx.x; c < 512; c += blockDim.x)
            woh[o*512 + c] = __float2half_rn(wo[o*512 + c] * s);
        if (threadIdx.x == 0) bof[o] = bo[o]*s + b2[o] - m2[o]*s;
    }
}

__global__ void init_rmax(u32* r){
    int t = blockIdx.x*256 + threadIdx.x;
    if (t < NB*TN) r[t] = 0u;
}

__global__ void conv_x(const float* __restrict__ x, __half* __restrict__ xh)
{
    __shared__ float t[32][33];
    const int z = blockIdx.z;
    const float* xb = x + (size_t)z*512*TN;
    const int n0 = blockIdx.x*32, c0 = blockIdx.y*32;
    const int tx = threadIdx.x, ty = threadIdx.y;
#pragma unroll
    for (int i=0;i<4;i++)
        t[ty + i*8][tx] = xb[(size_t)(c0 + ty + i*8)*TN + n0 + tx];
    __syncthreads();
#pragma unroll
    for (int i=0;i<4;i++){
        int n = n0 + ty + i*8, c = c0 + tx;
        xh[((size_t)z*TN + n)*512 + c] = __float2half_rn(t[tx][ty + i*8]);
    }
}

// ---------------- launch ----------------------------------------------------
#define DSMEM_TC  98304
#define DSMEM_SYM 98304
#define DSMEM_CTX (3*40960 + 256)

extern "C" void kernel_launch(void* const* d_in, const int* in_sizes, int n_in,
                              void* d_out, int out_size)
{
    const float* x  = (const float*)d_in[0];
    const float* wk = (const float*)d_in[1];
    const float* bk = (const float*)d_in[2];
    const float* g1 = (const float*)d_in[3];
    const float* b1 = (const float*)d_in[4];
    const float* m1 = (const float*)d_in[5];
    const float* v1 = (const float*)d_in[6];
    const float* wv = (const float*)d_in[7];
    const float* bv = (const float*)d_in[8];
    const float* wW = (const float*)d_in[9];
    const float* bW = (const float*)d_in[10];
    const float* wo = (const float*)d_in[11];
    const float* bo = (const float*)d_in[12];
    const float* g2 = (const float*)d_in[13];
    const float* b2 = (const float*)d_in[14];
    const float* m2 = (const float*)d_in[15];
    const float* v2 = (const float*)d_in[16];
    float* out = (float*)d_out;

    cudaFuncSetAttribute(gemm_tc,        cudaFuncAttributeMaxDynamicSharedMemorySize, DSMEM_TC);
    cudaFuncSetAttribute(gemm_sym,       cudaFuncAttributeMaxDynamicSharedMemorySize, DSMEM_SYM);
    cudaFuncSetAttribute(gemm_ctx_fused, cudaFuncAttributeMaxDynamicSharedMemorySize, DSMEM_CTX);

    __half *xh,*kh,*vh,*ch,*c2h,*wkh,*wvh,*wWh,*woh;
    float *att,*bkf,*bof; u32 *rmx;
    cudaGetSymbolAddress((void**)&xh, g_xh);
    cudaGetSymbolAddress((void**)&kh, g_kh);
    cudaGetSymbolAddress((void**)&vh, g_vh);
    cudaGetSymbolAddress((void**)&att, g_att);
    cudaGetSymbolAddress((void**)&ch, g_ch);
    cudaGetSymbolAddress((void**)&c2h, g_c2h);
    cudaGetSymbolAddress((void**)&wkh, g_wkh);
    cudaGetSymbolAddress((void**)&wvh, g_wvh);
    cudaGetSymbolAddress((void**)&wWh, g_wWh);
    cudaGetSymbolAddress((void**)&woh, g_woh);
    cudaGetSymbolAddress((void**)&bkf, g_bkf);
    cudaGetSymbolAddress((void**)&bof, g_bof);
    cudaGetSymbolAddress((void**)&rmx, g_rmax);

    // launches 0-2
    prep_all<<<dim3(512,4), 256>>>(wk, bk, g1, b1, m1, v1, wv, wW, wo, bo, g2, b2, m2, v2,
                                   wkh, bkf, wvh, wWh, woh, bof);
    conv_x<<<dim3(TN/32, 16, NB), dim3(32,8)>>>(x, xh);
    init_rmax<<<(NB*TN + 255)/256, 256>>>(rmx);

    // 3: k_t[n][cout] = relu(Wk_f x + bk_f)
    gemm_tc<<<dim3(72,4,NB), 256, DSMEM_TC>>>(xh, (size_t)TN*512, 512,
        wkh, 0, 512, 512, F_BCOL|F_RELU, bkf,
        kh, nullptr, (size_t)TN*512, 512);
    // 4: val[v][n] = Wv x + bv
    gemm_tc<<<dim3(2,72,NB), 256, DSMEM_TC>>>(wvh, 0, 512,
        xh, (size_t)TN*512, 512, 512, F_BROW, bv,
        vh, nullptr, (size_t)256*TN, TN);
    // 5: sim (symmetric, fp16 1-pass, fp32 out)
    gemm_sym<<<dim3(2628,1,NB), 256, DSMEM_SYM>>>(kh, 0.0441941738241592f, att, rmx);
    // 6: ctx with fused exp/rowsum/normalize (512 threads, 16 warps)
    gemm_ctx_fused<<<dim3(TN/64,1,NB), 512, DSMEM_CTX>>>(att, vh, rmx, ch);
    // 7: ctx2[n][co] = wW ctx + bW
    gemm_tc<<<dim3(72,4,NB), 256, DSMEM_TC>>>(ch, (size_t)TN*256, 256,
        wWh, 0, 256, 256, F_BCOL, bW,
        c2h, nullptr, (size_t)TN*512, 512);
    // 8: out[co][n] = relu(wo_f ctx2 + bo_f), fp32
    gemm_tc<<<dim3(4,72,NB), 256, DSMEM_TC>>>(woh, 0, 512,
        c2h, (size_t)TN*512, 512, 512, F_BROW|F_RELU|F_F32, bof,
        nullptr, out, (size_t)512*TN, TN);
}

// round 14
// speedup vs baseline: 1.0425x; 1.0425x over previous
#include <cuda_runtime.h>
#include <cuda_fp16.h>
#include <math.h>
#include <stdint.h>

#define TN 9216
#define NB 2
typedef unsigned int u32;
typedef unsigned long long u64;

#define F_RELU   1
#define F_BROW   2
#define F_BCOL   4
#define F_F32    16

// ---------------- scratch (static device arrays; no cudaMalloc allowed) ----
__device__ __half g_xh[(size_t)NB*TN*512];
__device__ __half g_kh[(size_t)NB*TN*512];
__device__ __half g_vh[(size_t)NB*256*TN];
__device__ float  g_att[(size_t)NB*TN*TN];      // 680 MB fp32 sim
__device__ __half g_ch[(size_t)NB*TN*256];
__device__ __half g_wkh[512*512];
__device__ __half g_wvh[256*512];
__device__ __half g_wWh[512*256];
__device__ __half g_wWT[256*512];               // wW transposed (c-major -> m-major)
__device__ __half g_woh[512*512];
__device__ __half g_wcomb[512*256];             // wo_f · wW, fp16
__device__ float g_bkf[512], g_bcomb[512];
__device__ u32   g_rmax[NB*TN];

// ---------------- helpers ----------------------------------------------------
static __device__ __forceinline__ u32 smem_u32(const void* p){
    u32 a;
    asm("{ .reg .u64 t; cvta.to.shared.u64 t, %1; cvt.u32.u64 %0, t; }" : "=r"(a) : "l"(p));
    return a;
}
static __device__ __forceinline__ void cpasync16(u32 s, const void* g){
    asm volatile("cp.async.cg.shared.global [%0], [%1], 16;" :: "r"(s), "l"(g) : "memory");
}
#define CP_COMMIT() asm volatile("cp.async.commit_group;" ::: "memory")
#define CP_WAIT0()  asm volatile("cp.async.wait_group 0;" ::: "memory")
#define CP_WAIT1()  asm volatile("cp.async.wait_group 1;" ::: "memory")

static __device__ __forceinline__ void ldsm4(u32& r0, u32& r1, u32& r2, u32& r3, u32 a){
    asm volatile("ldmatrix.sync.aligned.m8n8.x4.shared.b16 {%0,%1,%2,%3}, [%4];"
                 : "=r"(r0), "=r"(r1), "=r"(r2), "=r"(r3) : "r"(a));
}
static __device__ __forceinline__ void mma16816(float* d, const u32* a, const u32* b){
    asm volatile("mma.sync.aligned.m16n8k16.row.col.f32.f16.f16.f32 "
                 "{%0,%1,%2,%3}, {%4,%5,%6,%7}, {%8,%9}, {%0,%1,%2,%3};"
                 : "+f"(d[0]), "+f"(d[1]), "+f"(d[2]), "+f"(d[3])
                 : "r"(a[0]), "r"(a[1]), "r"(a[2]), "r"(a[3]), "r"(b[0]), "r"(b[1]));
}
static __device__ __forceinline__ u32 fenc(float f){
    u32 u = __float_as_uint(f);
    return (u & 0x80000000u) ? ~u : (u | 0x80000000u);
}
static __device__ __forceinline__ float fdec(u32 u){
    return (u & 0x80000000u) ? __uint_as_float(u ^ 0x80000000u) : __uint_as_float(~u);
}

// ---------------- single-pass fp16 tensor GEMM (3-stage, 2 CTAs/SM) ----------
__global__ void __launch_bounds__(256,2) gemm_tc(
    const __half* __restrict__ a, size_t a_bs, int lda,
    const __half* __restrict__ b, size_t b_bs, int ldb,
    int K, int flags, const float* __restrict__ bias,
    __half* oh, float* of, size_t o_bs, int ldo)
{
    extern __shared__ char dsm[];
    const int tid = threadIdx.x, wid = tid>>5, lid = tid&31;
    const int m0 = blockIdx.x*128, n0 = blockIdx.y*128, z = blockIdx.z;
    a += (size_t)z*a_bs; b += (size_t)z*b_bs;
    const int wm = wid>>2, wn = wid&3;
    const u32 sb = smem_u32(dsm);
    const int lrow = tid>>3, lc = tid&7;

    float acc[4][4][4];
#pragma unroll
    for (int i=0;i<4;i++)
#pragma unroll
        for (int j=0;j<4;j++)
#pragma unroll
            for (int q=0;q<4;q++) acc[i][j][q] = 0.f;

    const int S = K >> 6;
    auto issue = [&](int s){
        const int k0 = s << 6;
        const u32 bufo = (u32)(s % 3) * 32768u;
#pragma unroll
        for (int arr=0; arr<2; arr++){
            const __half* gp = arr ? b : a;
            const int rb = arr ? n0 : m0;
            const int ld = arr ? ldb : lda;
            const u32 so = sb + bufo + arr*16384u;
#pragma unroll
            for (int i=0;i<4;i++){
                const int row = lrow + i*32;
                const void* g = gp + (size_t)(rb+row)*ld + k0 + lc*8;
                const u32 sa = so + (u32)(row*128) + (u32)((lc ^ (row&7)) << 4);
                cpasync16(sa, g);
            }
        }
        CP_COMMIT();
    };

    issue(0);
    issue(1);
    for (int s=0; s<S; s++){
        if (s+1 < S) { CP_WAIT1(); } else { CP_WAIT0(); }
        __syncthreads();
        if (s+2 < S) issue(s+2);
        const u32 bufo = (u32)(s % 3) * 32768u;
        const u32 bA = sb+bufo, bB = sb+bufo+16384u;
        const int prA = (wm*64 + (lid&15)) * 128;
        const int prB0 = (wn*32 +      (lid&7) + ((lid>>4)<<3)) * 128;
        const int prB1 = (wn*32 + 16 + (lid&7) + ((lid>>4)<<3)) * 128;
#pragma unroll
        for (int st=0; st<4; st++){
            u32 Ah[4][4], Bh[4][2];
            const int xa = ((st*2 + (lid>>4))    ^ (lid&7)) << 4;
            const int xb = ((st*2 + ((lid>>3)&1)) ^ (lid&7)) << 4;
#pragma unroll
            for (int i=0;i<4;i++)
                ldsm4(Ah[i][0],Ah[i][1],Ah[i][2],Ah[i][3], bA + prA + i*2048 + xa);
            {
                u32 r0,r1,r2,r3;
                ldsm4(r0,r1,r2,r3, bB + prB0 + xb);
                Bh[0][0]=r0; Bh[0][1]=r1; Bh[1][0]=r2; Bh[1][1]=r3;
                ldsm4(r0,r1,r2,r3, bB + prB1 + xb);
                Bh[2][0]=r0; Bh[2][1]=r1; Bh[3][0]=r2; Bh[3][1]=r3;
            }
#pragma unroll
            for (int i=0;i<4;i++)
#pragma unroll
                for (int j=0;j<4;j++) mma16816(acc[i][j], Ah[i], Bh[j]);
        }
    }

    const int tr = lid>>2, tc = (lid&3)*2;
    const int mBase = m0 + wm*64, nBase = n0 + wn*32;
#pragma unroll
    for (int i=0;i<4;i++){
#pragma unroll
        for (int hh=0; hh<2; hh++){
            const int row = mBase + i*16 + tr + hh*8;
            float brow = (flags & F_BROW) ? bias[row] : 0.f;
            if (flags & F_F32){
                float* op = of + (size_t)z*o_bs + (size_t)row*ldo;
#pragma unroll
                for (int j=0;j<4;j++){
                    const int n = nBase + j*8 + tc;
                    float v0 = acc[i][j][hh*2+0] + brow;
                    float v1 = acc[i][j][hh*2+1] + brow;
                    if (flags & F_BCOL){ v0 += bias[n]; v1 += bias[n+1]; }
                    if (flags & F_RELU){ v0 = fmaxf(v0,0.f); v1 = fmaxf(v1,0.f); }
                    float2 w; w.x = v0; w.y = v1;
                    *(float2*)(op + n) = w;
                }
            } else {
                __half* oph = oh + (size_t)z*o_bs + (size_t)row*ldo;
#pragma unroll
                for (int j=0;j<4;j++){
                    const int n = nBase + j*8 + tc;
                    float v0 = acc[i][j][hh*2+0] + brow;
                    float v1 = acc[i][j][hh*2+1] + brow;
                    if (flags & F_BCOL){ v0 += bias[n]; v1 += bias[n+1]; }
                    if (flags & F_RELU){ v0 = fmaxf(v0,0.f); v1 = fmaxf(v1,0.f); }
                    *(__half2*)(oph + n) = __floats2half2_rn(v0, v1);
                }
            }
        }
    }
}

// ---------------- symmetric sim GEMM: fp16 1-pass, fp32 out, 3-stage ---------
__global__ void __launch_bounds__(256,2) gemm_sym(
    const __half* __restrict__ kh,
    float scale, float* __restrict__ att, u32* __restrict__ rmaxU)
{
    extern __shared__ char dsm[];
    const int tid = threadIdx.x, wid = tid>>5, lid = tid&31;
    const int z = blockIdx.z;
    const int t = blockIdx.x;
    int i = (int)((145.0f - sqrtf(21025.0f - 8.0f*(float)t)) * 0.5f);
    while (i > 0 && i*72 - i*(i-1)/2 > t) i--;
    while ((i+1)*72 - (i+1)*i/2 <= t) i++;
    const int j = i + (t - (i*72 - i*(i-1)/2));
    const int m0 = i*128, n0 = j*128;

    const __half* ah = kh + (size_t)z*TN*512;
    const int wm = wid>>2, wn = wid&3;
    const u32 sb = smem_u32(dsm);
    const int lrow = tid>>3, lc = tid&7;

    float acc[4][4][4];
#pragma unroll
    for (int a=0;a<4;a++)
#pragma unroll
        for (int b=0;b<4;b++)
#pragma unroll
            for (int q=0;q<4;q++) acc[a][b][q] = 0.f;

    auto issue = [&](int s){
        const int k0 = s << 6;
        const u32 bufo = (u32)(s % 3) * 32768u;
#pragma unroll
        for (int arr=0; arr<2; arr++){
            const int rb = arr ? n0 : m0;
            const u32 so = sb + bufo + arr*16384u;
#pragma unroll
            for (int q=0;q<4;q++){
                const int row = lrow + q*32;
                const void* g = ah + (size_t)(rb+row)*512 + k0 + lc*8;
                const u32 sa = so + (u32)(row*128) + (u32)((lc ^ (row&7)) << 4);
                cpasync16(sa, g);
            }
        }
        CP_COMMIT();
    };

    issue(0); issue(1);
    for (int s=0; s<8; s++){
        if (s+1 < 8) { CP_WAIT1(); } else { CP_WAIT0(); }
        __syncthreads();
        if (s+2 < 8) issue(s+2);
        const u32 bufo = (u32)(s % 3) * 32768u;
        const u32 bA = sb+bufo, bB = sb+bufo+16384u;
        const int prA = (wm*64 + (lid&15)) * 128;
        const int prB0 = (wn*32 +      (lid&7) + ((lid>>4)<<3)) * 128;
        const int prB1 = (wn*32 + 16 + (lid&7) + ((lid>>4)<<3)) * 128;
#pragma unroll
        for (int st=0; st<4; st++){
            u32 Ah[4][4], Bh[4][2];
            const int xa = ((st*2 + (lid>>4))    ^ (lid&7)) << 4;
            const int xb = ((st*2 + ((lid>>3)&1)) ^ (lid&7)) << 4;
#pragma unroll
            for (int a=0;a<4;a++)
                ldsm4(Ah[a][0],Ah[a][1],Ah[a][2],Ah[a][3], bA + prA + a*2048 + xa);
            {
                u32 r0,r1,r2,r3;
                ldsm4(r0,r1,r2,r3, bB + prB0 + xb);
                Bh[0][0]=r0; Bh[0][1]=r1; Bh[1][0]=r2; Bh[1][1]=r3;
                ldsm4(r0,r1,r2,r3, bB + prB1 + xb);
                Bh[2][0]=r0; Bh[2][1]=r1; Bh[3][0]=r2; Bh[3][1]=r3;
            }
#pragma unroll
            for (int a=0;a<4;a++)
#pragma unroll
                for (int b=0;b<4;b++) mma16816(acc[a][b], Ah[a], Bh[b]);
        }
    }

    // stage scaled fp32 tile (stride 129 floats — scalar LDS only!)
    __syncthreads();
    float* Sm = (float*)dsm;
    float* P  = Sm + 128*129;
    const int tr = lid>>2, tc = (lid&3)*2;
#pragma unroll
    for (int a=0;a<4;a++)
#pragma unroll
        for (int hh=0; hh<2; hh++){
            const int rl = wm*64 + a*16 + tr + hh*8;
#pragma unroll
            for (int b=0;b<4;b++){
                const int cl = wn*32 + b*8 + tc;
                Sm[rl*129 + cl]     = acc[a][b][hh*2+0]*scale;
                Sm[rl*129 + cl + 1] = acc[a][b][hh*2+1]*scale;
            }
        }
    __syncthreads();

    const int rr = tid & 127, hf2 = tid >> 7;
    {
        float m = -1e30f;
        for (int c=0;c<64;c++) m = fmaxf(m, Sm[rr*129 + hf2*64 + c]);
        P[rr*2 + hf2] = m;
    }
    __syncthreads();
    if (tid < 128) atomicMax(&rmaxU[(size_t)z*TN + m0 + tid], fenc(fmaxf(P[tid*2], P[tid*2+1])));
    __syncthreads();
    {
        float m = -1e30f;
        for (int r2=0;r2<64;r2++) m = fmaxf(m, Sm[(hf2*64 + r2)*129 + rr]);
        P[rr*2 + hf2] = m;
    }
    __syncthreads();
    if (tid < 128) atomicMax(&rmaxU[(size_t)z*TN + n0 + tid], fenc(fmaxf(P[tid*2], P[tid*2+1])));

    const size_t obase = (size_t)z*TN*TN;
    {
        const int r = tid>>1, c0 = (tid&1)*64;
        float* op = att + obase + (size_t)(m0 + r)*TN + n0 + c0;
        const float* Sr = Sm + r*129 + c0;
#pragma unroll
        for (int it=0; it<16; it++){
            float4 w;
            w.x = Sr[it*4 + 0];
            w.y = Sr[it*4 + 1];
            w.z = Sr[it*4 + 2];
            w.w = Sr[it*4 + 3];
            *(float4*)(op + it*4) = w;
        }
    }
    if (i != j){
        const int c = tid>>1, r0 = (tid&1)*64;
        float* op = att + obase + (size_t)(n0 + c)*TN + m0 + r0;
#pragma unroll
        for (int it=0; it<16; it++){
            float4 w;
            w.x = Sm[(r0 + it*4 + 0)*129 + c];
            w.y = Sm[(r0 + it*4 + 1)*129 + c];
            w.z = Sm[(r0 + it*4 + 2)*129 + c];
            w.w = Sm[(r0 + it*4 + 3)*129 + c];
            *(float4*)(op + it*4) = w;
        }
    }
}

// ---------------- fused exp/rowsum/normalize ctx GEMM (R12: 256 thr) ---------
#define CTX_STAGE 40960u
__global__ void __launch_bounds__(256,1) gemm_ctx_fused(
    const float* __restrict__ att,
    const __half* __restrict__ vh,
    const u32* __restrict__ rmaxU,
    __half* __restrict__ ch)
{
    extern __shared__ char dsm[];
    const int tid = threadIdx.x, wid = tid>>5, lid = tid&31;
    const int z = blockIdx.z;
    const int n0 = blockIdx.x*64;
    const size_t abase = (size_t)z*TN*TN;
    const __half* vhb = vh + (size_t)z*256*TN;
    const u32 sb = smem_u32(dsm);
    float* srow = (float*)(dsm + 3*CTX_STAGE);

    const int wm = wid>>2, wn = wid&3;
    const int lr = tid>>3, lc = tid&7;

    const float mx0 = fdec(rmaxU[(size_t)z*TN + n0 + lr]);
    const float mx1 = fdec(rmaxU[(size_t)z*TN + n0 + lr + 32]);
    const float* pA0 = att + abase + (size_t)(n0+lr)*TN + lc*8;
    const float* pA1 = pA0 + (size_t)32*TN;

    float acc[2][8][4];
#pragma unroll
    for (int i=0;i<2;i++)
#pragma unroll
        for (int j=0;j<8;j++)
#pragma unroll
            for (int q=0;q<4;q++) acc[i][j][q] = 0.f;
    float s0 = 0.f, s1 = 0.f;

    const int S = TN/64;   // 144
    __align__(16) float raf[16];
    auto ldgA = [&](int s){
        const int k0 = s<<6;
        *(uint4*)&raf[0]  = *(const uint4*)(pA0 + k0);
        *(uint4*)&raf[4]  = *(const uint4*)(pA0 + k0 + 4);
        *(uint4*)&raf[8]  = *(const uint4*)(pA1 + k0);
        *(uint4*)&raf[12] = *(const uint4*)(pA1 + k0 + 4);
    };
    auto issueB = [&](int s){
        const int k0 = s<<6;
        const u32 so = sb + (u32)(s%3)*CTX_STAGE + 8192u;
#pragma unroll
        for (int i=0;i<8;i++){
            const int row = lr + i*32;
            cpasync16(so + (u32)(row*128) + (u32)((lc ^ (row&7)) << 4),
                      vhb + (size_t)row*TN + k0 + lc*8);
        }
        CP_COMMIT();
    };
    auto exp8h = [&](const float* f, float mxv, float& ssum)->uint4{
        uint4 r;
        float e0, e1;
        e0 = __expf(f[0] - mxv); e1 = __expf(f[1] - mxv); ssum += e0 + e1;
        { __half2 h = __floats2half2_rn(e0, e1); r.x = *(u32*)&h; }
        e0 = __expf(f[2] - mxv); e1 = __expf(f[3] - mxv); ssum += e0 + e1;
        { __half2 h = __floats2half2_rn(e0, e1); r.y = *(u32*)&h; }
        e0 = __expf(f[4] - mxv); e1 = __expf(f[5] - mxv); ssum += e0 + e1;
        { __half2 h = __floats2half2_rn(e0, e1); r.z = *(u32*)&h; }
        e0 = __expf(f[6] - mxv); e1 = __expf(f[7] - mxv); ssum += e0 + e1;
        { __half2 h = __floats2half2_rn(e0, e1); r.w = *(u32*)&h; }
        return r;
    };
    const int aoff = lr*128 + ((lc ^ (lr&7)) << 4);

    ldgA(0);
    {
        uint4 h0 = exp8h(&raf[0], mx0, s0);
        uint4 h1 = exp8h(&raf[8], mx1, s1);
        *(uint4*)(dsm + aoff)        = h0;
        *(uint4*)(dsm + aoff + 4096) = h1;
    }
    issueB(0);
    issueB(1);

    for (int s=0; s<S; s++){
        if (s+1 < S) ldgA(s+1);
        if (s+1 < S) { CP_WAIT1(); } else { CP_WAIT0(); }
        __syncthreads();
        if (s+2 < S) issueB(s+2);

        const u32 bufo = (u32)(s%3)*CTX_STAGE;
        const u32 bA = sb + bufo, bB = sb + bufo + 8192u;
#pragma unroll
        for (int st=0; st<4; st++){
            u32 Ah[2][4], Bh[8][2];
            const int xa = ((st*2 + (lid>>4))    ^ (lid&7)) << 4;
            const int xb = ((st*2 + ((lid>>3)&1)) ^ (lid&7)) << 4;
#pragma unroll
            for (int i=0;i<2;i++){
                const u32 pr = (u32)((wm*32 + i*16 + (lid&15)) * 128);
                ldsm4(Ah[i][0],Ah[i][1],Ah[i][2],Ah[i][3], bA + pr + xa);
            }
#pragma unroll
            for (int j2=0; j2<4; j2++){
                const u32 pr = (u32)((wn*64 + j2*16 + (lid&7) + ((lid>>4)<<3)) * 128);
                u32 r0,r1,r2,r3;
                ldsm4(r0,r1,r2,r3, bB + pr + xb);
                Bh[2*j2][0]=r0; Bh[2*j2][1]=r1; Bh[2*j2+1][0]=r2; Bh[2*j2+1][1]=r3;
            }
#pragma unroll
            for (int i=0;i<2;i++)
#pragma unroll
                for (int j=0;j<8;j++) mma16816(acc[i][j], Ah[i], Bh[j]);
        }

        if (s+1 < S){
            const int off2 = (int)((u32)((s+1)%3)*CTX_STAGE) + aoff;
            uint4 h0 = exp8h(&raf[0], mx0, s0);
            uint4 h1 = exp8h(&raf[8], mx1, s1);
            *(uint4*)(dsm + off2)        = h0;
            *(uint4*)(dsm + off2 + 4096) = h1;
        }
    }

#pragma unroll
    for (int o=1;o<8;o<<=1){
        s0 += __shfl_xor_sync(0xffffffffu, s0, o);
        s1 += __shfl_xor_sync(0xffffffffu, s1, o);
    }
    __syncthreads();
    if ((tid&7)==0){ srow[lr] = s0; srow[lr+32] = s1; }
    __syncthreads();

    const int tr = lid>>2, tc2 = (lid&3)*2;
#pragma unroll
    for (int i=0;i<2;i++){
#pragma unroll
        for (int hh=0; hh<2; hh++){
            const int rowl = wm*32 + i*16 + tr + hh*8;
            const float inv = 1.0f / srow[rowl];
            const int row = n0 + rowl;
            __half* oph = ch + (size_t)z*TN*256 + (size_t)row*256 + wn*64;
#pragma unroll
            for (int j=0;j<8;j++){
                const int col = j*8 + tc2;
                *(__half2*)(oph + col) =
                    __floats2half2_rn(acc[i][j][hh*2+0]*inv, acc[i][j][hh*2+1]*inv);
            }
        }
    }
}

// ---------------- merged prep (single fp16 weights + wW transpose) -----------
__global__ void prep_all(
    const float* __restrict__ wk, const float* __restrict__ bk,
    const float* __restrict__ g1, const float* __restrict__ b1,
    const float* __restrict__ m1, const float* __restrict__ v1,
    const float* __restrict__ wv,
    const float* __restrict__ wW,
    const float* __restrict__ wo,
    const float* __restrict__ g2, const float* __restrict__ v2,
    __half* __restrict__ wkh, float* __restrict__ bkf,
    __half* __restrict__ wvh,
    __half* __restrict__ wWh, __half* __restrict__ wWT,
    __half* __restrict__ woh)
{
    const int o = blockIdx.x, which = blockIdx.y;
    if (which == 0){
        float s = g1[o] * rsqrtf(v1[o] + 1e-5f);
        for (int c = threadIdx.x; c < 512; c += blockDim.x)
            wkh[o*512 + c] = __float2half_rn(wk[o*512 + c] * s);
        if (threadIdx.x == 0) bkf[o] = bk[o]*s + b1[o] - m1[o]*s;
    } else if (which == 1){
        if (o < 256)
            for (int c = threadIdx.x; c < 512; c += blockDim.x)
                wvh[o*512 + c] = __float2half_rn(wv[o*512 + c]);
    } else if (which == 2){
        // wW row o (512 rows x 256 cols): normal + transposed copies
        for (int c = threadIdx.x; c < 256; c += blockDim.x){
            __half h = __float2half_rn(wW[o*256 + c]);
            wWh[o*256 + c] = h;
            wWT[c*512 + o] = h;
        }
    } else {
        float s = g2[o] * rsqrtf(v2[o] + 1e-5f);
        for (int c = threadIdx.x; c < 512; c += blockDim.x)
            woh[o*512 + c] = __float2half_rn(wo[o*512 + c] * s);
    }
}

// bcomb[o] = sum_m wo_f[o][m]*bW[m] + bo[o]*s + b2[o] - m2[o]*s
__global__ void __launch_bounds__(128) prep_bcomb(
    const float* __restrict__ wo, const float* __restrict__ bW,
    const float* __restrict__ bo,
    const float* __restrict__ g2, const float* __restrict__ b2,
    const float* __restrict__ m2, const float* __restrict__ v2,
    float* __restrict__ bcomb)
{
    const int o = blockIdx.x, tid = threadIdx.x;
    __shared__ float red[4];
    const float s = g2[o] * rsqrtf(v2[o] + 1e-5f);
    float acc = 0.f;
    for (int m = tid; m < 512; m += 128)
        acc += wo[o*512 + m] * bW[m];
#pragma unroll
    for (int off=16; off; off>>=1) acc += __shfl_xor_sync(0xffffffffu, acc, off);
    if ((tid&31)==0) red[tid>>5] = acc;
    __syncthreads();
    if (tid==0)
        bcomb[o] = (red[0]+red[1]+red[2]+red[3])*s + bo[o]*s + b2[o] - m2[o]*s;
}

__global__ void init_rmax(u32* r){
    int t = blockIdx.x*256 + threadIdx.x;
    if (t < NB*TN) r[t] = 0u;
}

__global__ void conv_x(const float* __restrict__ x, __half* __restrict__ xh)
{
    __shared__ float t[32][33];
    const int z = blockIdx.z;
    const float* xb = x + (size_t)z*512*TN;
    const int n0 = blockIdx.x*32, c0 = blockIdx.y*32;
    const int tx = threadIdx.x, ty = threadIdx.y;
#pragma unroll
    for (int i=0;i<4;i++)
        t[ty + i*8][tx] = xb[(size_t)(c0 + ty + i*8)*TN + n0 + tx];
    __syncthreads();
#pragma unroll
    for (int i=0;i<4;i++){
        int n = n0 + ty + i*8, c = c0 + tx;
        xh[((size_t)z*TN + n)*512 + c] = __float2half_rn(t[tx][ty + i*8]);
    }
}

// ---------------- launch ----------------------------------------------------
#define DSMEM_TC  98304
#define DSMEM_SYM 98304
#define DSMEM_CTX (3*40960 + 256)

extern "C" void kernel_launch(void* const* d_in, const int* in_sizes, int n_in,
                              void* d_out, int out_size)
{
    const float* x  = (const float*)d_in[0];
    const float* wk = (const float*)d_in[1];
    const float* bk = (const float*)d_in[2];
    const float* g1 = (const float*)d_in[3];
    const float* b1 = (const float*)d_in[4];
    const float* m1 = (const float*)d_in[5];
    const float* v1 = (const float*)d_in[6];
    const float* wv = (const float*)d_in[7];
    const float* bv = (const float*)d_in[8];
    const float* wW = (const float*)d_in[9];
    const float* bW = (const float*)d_in[10];
    const float* wo = (const float*)d_in[11];
    const float* bo = (const float*)d_in[12];
    const float* g2 = (const float*)d_in[13];
    const float* b2 = (const float*)d_in[14];
    const float* m2 = (const float*)d_in[15];
    const float* v2 = (const float*)d_in[16];
    float* out = (float*)d_out;

    cudaFuncSetAttribute(gemm_tc,        cudaFuncAttributeMaxDynamicSharedMemorySize, DSMEM_TC);
    cudaFuncSetAttribute(gemm_sym,       cudaFuncAttributeMaxDynamicSharedMemorySize, DSMEM_SYM);
    cudaFuncSetAttribute(gemm_ctx_fused, cudaFuncAttributeMaxDynamicSharedMemorySize, DSMEM_CTX);

    __half *xh,*kh,*vh,*ch,*wkh,*wvh,*wWh,*wWT,*woh,*wcomb;
    float *att,*bkf,*bcomb; u32 *rmx;
    cudaGetSymbolAddress((void**)&xh, g_xh);
    cudaGetSymbolAddress((void**)&kh, g_kh);
    cudaGetSymbolAddress((void**)&vh, g_vh);
    cudaGetSymbolAddress((void**)&att, g_att);
    cudaGetSymbolAddress((void**)&ch, g_ch);
    cudaGetSymbolAddress((void**)&wkh, g_wkh);
    cudaGetSymbolAddress((void**)&wvh, g_wvh);
    cudaGetSymbolAddress((void**)&wWh, g_wWh);
    cudaGetSymbolAddress((void**)&wWT, g_wWT);
    cudaGetSymbolAddress((void**)&woh, g_woh);
    cudaGetSymbolAddress((void**)&wcomb, g_wcomb);
    cudaGetSymbolAddress((void**)&bkf, g_bkf);
    cudaGetSymbolAddress((void**)&bcomb, g_bcomb);
    cudaGetSymbolAddress((void**)&rmx, g_rmax);

    // prep
    prep_all<<<dim3(512,4), 256>>>(wk, bk, g1, b1, m1, v1, wv, wW, wo, g2, v2,
                                   wkh, bkf, wvh, wWh, wWT, woh);
    prep_bcomb<<<512, 128>>>(wo, bW, bo, g2, b2, m2, v2, bcomb);
    conv_x<<<dim3(TN/32, 16, NB), dim3(32,8)>>>(x, xh);
    init_rmax<<<(NB*TN + 255)/256, 256>>>(rmx);

    // wcomb[o][c] = sum_m woh[o][m] * wWT[c][m]   (512x256, K=512)
    gemm_tc<<<dim3(4,2,1), 256, DSMEM_TC>>>(woh, 0, 512,
        wWT, 0, 512, 512, 0, nullptr,
        wcomb, nullptr, 0, 256);

    // k_t[n][cout] = relu(Wk_f x + bk_f)
    gemm_tc<<<dim3(72,4,NB), 256, DSMEM_TC>>>(xh, (size_t)TN*512, 512,
        wkh, 0, 512, 512, F_BCOL|F_RELU, bkf,
        kh, nullptr, (size_t)TN*512, 512);
    // val[v][n] = Wv x + bv
    gemm_tc<<<dim3(2,72,NB), 256, DSMEM_TC>>>(wvh, 0, 512,
        xh, (size_t)TN*512, 512, 512, F_BROW, bv,
        vh, nullptr, (size_t)256*TN, TN);
    // sim (symmetric, fp16 1-pass, fp32 out)
    gemm_sym<<<dim3(2628,1,NB), 256, DSMEM_SYM>>>(kh, 0.0441941738241592f, att, rmx);
    // ctx with fused exp/rowsum/normalize (R12 256-thread version)
    gemm_ctx_fused<<<dim3(TN/64,1,NB), 256, DSMEM_CTX>>>(att, vh, rmx, ch);
    // out[co][n] = relu(wcomb·ctx + bcomb), fp32  (merged wW+wo convs)
    gemm_tc<<<dim3(4,72,NB), 256, DSMEM_TC>>>(wcomb, 0, 256,
        ch, (size_t)TN*256, 256, 256, F_BROW|F_RELU|F_F32, bcomb,
        nullptr, out, (size_t)512*TN, TN);
}

// round 15
// speedup vs baseline: 1.0993x; 1.0545x over previous
#include <cuda_runtime.h>
#include <cuda_fp16.h>
#include <math.h>
#include <stdint.h>

#define TN 9216
#define NB 2
typedef unsigned int u32;
typedef unsigned long long u64;

#define F_RELU   1
#define F_BROW   2
#define F_BCOL   4
#define F_F32    16

// ---------------- scratch (static device arrays; no cudaMalloc allowed) ----
__device__ __half g_xh[(size_t)NB*TN*512];
__device__ __half g_kh[(size_t)NB*TN*512];
__device__ __half g_vh[(size_t)NB*256*TN];
__device__ float  g_att[(size_t)NB*TN*TN];      // 680 MB fp32 sim
__device__ __half g_ch[(size_t)NB*TN*256];
__device__ __half g_wkh[512*512];
__device__ __half g_wvh[256*512];
__device__ __half g_wWT[256*512];               // wW transposed
__device__ __half g_woh[512*512];
__device__ __half g_wcomb[512*256];             // wo_f · wW, fp16
__device__ float g_bkf[512], g_bcomb[512];
__device__ u32   g_rmax[NB*TN];

// ---------------- helpers ----------------------------------------------------
static __device__ __forceinline__ u32 smem_u32(const void* p){
    u32 a;
    asm("{ .reg .u64 t; cvta.to.shared.u64 t, %1; cvt.u32.u64 %0, t; }" : "=r"(a) : "l"(p));
    return a;
}
static __device__ __forceinline__ void cpasync16(u32 s, const void* g){
    asm volatile("cp.async.cg.shared.global [%0], [%1], 16;" :: "r"(s), "l"(g) : "memory");
}
#define CP_COMMIT() asm volatile("cp.async.commit_group;" ::: "memory")
#define CP_WAIT0()  asm volatile("cp.async.wait_group 0;" ::: "memory")
#define CP_WAIT1()  asm volatile("cp.async.wait_group 1;" ::: "memory")

static __device__ __forceinline__ void ldsm4(u32& r0, u32& r1, u32& r2, u32& r3, u32 a){
    asm volatile("ldmatrix.sync.aligned.m8n8.x4.shared.b16 {%0,%1,%2,%3}, [%4];"
                 : "=r"(r0), "=r"(r1), "=r"(r2), "=r"(r3) : "r"(a));
}
static __device__ __forceinline__ void mma16816(float* d, const u32* a, const u32* b){
    asm volatile("mma.sync.aligned.m16n8k16.row.col.f32.f16.f16.f32 "
                 "{%0,%1,%2,%3}, {%4,%5,%6,%7}, {%8,%9}, {%0,%1,%2,%3};"
                 : "+f"(d[0]), "+f"(d[1]), "+f"(d[2]), "+f"(d[3])
                 : "r"(a[0]), "r"(a[1]), "r"(a[2]), "r"(a[3]), "r"(b[0]), "r"(b[1]));
}
static __device__ __forceinline__ u32 fenc(float f){
    u32 u = __float_as_uint(f);
    return (u & 0x80000000u) ? ~u : (u | 0x80000000u);
}
static __device__ __forceinline__ float fdec(u32 u){
    return (u & 0x80000000u) ? __uint_as_float(u ^ 0x80000000u) : __uint_as_float(~u);
}

// ---------------- single-pass fp16 tensor GEMM (3-stage, 2 CTAs/SM) ----------
__global__ void __launch_bounds__(256,2) gemm_tc(
    const __half* __restrict__ a, size_t a_bs, int lda,
    const __half* __restrict__ b, size_t b_bs, int ldb,
    int K, int flags, const float* __restrict__ bias,
    __half* oh, float* of, size_t o_bs, int ldo)
{
    extern __shared__ char dsm[];
    const int tid = threadIdx.x, wid = tid>>5, lid = tid&31;
    const int m0 = blockIdx.x*128, n0 = blockIdx.y*128, z = blockIdx.z;
    a += (size_t)z*a_bs; b += (size_t)z*b_bs;
    const int wm = wid>>2, wn = wid&3;
    const u32 sb = smem_u32(dsm);
    const int lrow = tid>>3, lc = tid&7;

    float acc[4][4][4];
#pragma unroll
    for (int i=0;i<4;i++)
#pragma unroll
        for (int j=0;j<4;j++)
#pragma unroll
            for (int q=0;q<4;q++) acc[i][j][q] = 0.f;

    const int S = K >> 6;
    auto issue = [&](int s){
        const int k0 = s << 6;
        const u32 bufo = (u32)(s % 3) * 32768u;
#pragma unroll
        for (int arr=0; arr<2; arr++){
            const __half* gp = arr ? b : a;
            const int rb = arr ? n0 : m0;
            const int ld = arr ? ldb : lda;
            const u32 so = sb + bufo + arr*16384u;
#pragma unroll
            for (int i=0;i<4;i++){
                const int row = lrow + i*32;
                const void* g = gp + (size_t)(rb+row)*ld + k0 + lc*8;
                const u32 sa = so + (u32)(row*128) + (u32)((lc ^ (row&7)) << 4);
                cpasync16(sa, g);
            }
        }
        CP_COMMIT();
    };

    issue(0);
    issue(1);
    for (int s=0; s<S; s++){
        if (s+1 < S) { CP_WAIT1(); } else { CP_WAIT0(); }
        __syncthreads();
        if (s+2 < S) issue(s+2);
        const u32 bufo = (u32)(s % 3) * 32768u;
        const u32 bA = sb+bufo, bB = sb+bufo+16384u;
        const int prA = (wm*64 + (lid&15)) * 128;
        const int prB0 = (wn*32 +      (lid&7) + ((lid>>4)<<3)) * 128;
        const int prB1 = (wn*32 + 16 + (lid&7) + ((lid>>4)<<3)) * 128;
#pragma unroll
        for (int st=0; st<4; st++){
            u32 Ah[4][4], Bh[4][2];
            const int xa = ((st*2 + (lid>>4))    ^ (lid&7)) << 4;
            const int xb = ((st*2 + ((lid>>3)&1)) ^ (lid&7)) << 4;
#pragma unroll
            for (int i=0;i<4;i++)
                ldsm4(Ah[i][0],Ah[i][1],Ah[i][2],Ah[i][3], bA + prA + i*2048 + xa);
            {
                u32 r0,r1,r2,r3;
                ldsm4(r0,r1,r2,r3, bB + prB0 + xb);
                Bh[0][0]=r0; Bh[0][1]=r1; Bh[1][0]=r2; Bh[1][1]=r3;
                ldsm4(r0,r1,r2,r3, bB + prB1 + xb);
                Bh[2][0]=r0; Bh[2][1]=r1; Bh[3][0]=r2; Bh[3][1]=r3;
            }
#pragma unroll
            for (int i=0;i<4;i++)
#pragma unroll
                for (int j=0;j<4;j++) mma16816(acc[i][j], Ah[i], Bh[j]);
        }
    }

    const int tr = lid>>2, tc = (lid&3)*2;
    const int mBase = m0 + wm*64, nBase = n0 + wn*32;
#pragma unroll
    for (int i=0;i<4;i++){
#pragma unroll
        for (int hh=0; hh<2; hh++){
            const int row = mBase + i*16 + tr + hh*8;
            float brow = (flags & F_BROW) ? bias[row] : 0.f;
            if (flags & F_F32){
                float* op = of + (size_t)z*o_bs + (size_t)row*ldo;
#pragma unroll
                for (int j=0;j<4;j++){
                    const int n = nBase + j*8 + tc;
                    float v0 = acc[i][j][hh*2+0] + brow;
                    float v1 = acc[i][j][hh*2+1] + brow;
                    if (flags & F_BCOL){ v0 += bias[n]; v1 += bias[n+1]; }
                    if (flags & F_RELU){ v0 = fmaxf(v0,0.f); v1 = fmaxf(v1,0.f); }
                    float2 w; w.x = v0; w.y = v1;
                    *(float2*)(op + n) = w;
                }
            } else {
                __half* oph = oh + (size_t)z*o_bs + (size_t)row*ldo;
#pragma unroll
                for (int j=0;j<4;j++){
                    const int n = nBase + j*8 + tc;
                    float v0 = acc[i][j][hh*2+0] + brow;
                    float v1 = acc[i][j][hh*2+1] + brow;
                    if (flags & F_BCOL){ v0 += bias[n]; v1 += bias[n+1]; }
                    if (flags & F_RELU){ v0 = fmaxf(v0,0.f); v1 = fmaxf(v1,0.f); }
                    *(__half2*)(oph + n) = __floats2half2_rn(v0, v1);
                }
            }
        }
    }
}

// ---------------- symmetric sim GEMM: fp16 1-pass, fp32 out, 3-stage ---------
__global__ void __launch_bounds__(256,2) gemm_sym(
    const __half* __restrict__ kh,
    float scale, float* __restrict__ att, u32* __restrict__ rmaxU)
{
    extern __shared__ char dsm[];
    const int tid = threadIdx.x, wid = tid>>5, lid = tid&31;
    const int z = blockIdx.z;
    const int t = blockIdx.x;
    int i = (int)((145.0f - sqrtf(21025.0f - 8.0f*(float)t)) * 0.5f);
    while (i > 0 && i*72 - i*(i-1)/2 > t) i--;
    while ((i+1)*72 - (i+1)*i/2 <= t) i++;
    const int j = i + (t - (i*72 - i*(i-1)/2));
    const int m0 = i*128, n0 = j*128;

    const __half* ah = kh + (size_t)z*TN*512;
    const int wm = wid>>2, wn = wid&3;
    const u32 sb = smem_u32(dsm);
    const int lrow = tid>>3, lc = tid&7;

    float acc[4][4][4];
#pragma unroll
    for (int a=0;a<4;a++)
#pragma unroll
        for (int b=0;b<4;b++)
#pragma unroll
            for (int q=0;q<4;q++) acc[a][b][q] = 0.f;

    auto issue = [&](int s){
        const int k0 = s << 6;
        const u32 bufo = (u32)(s % 3) * 32768u;
#pragma unroll
        for (int arr=0; arr<2; arr++){
            const int rb = arr ? n0 : m0;
            const u32 so = sb + bufo + arr*16384u;
#pragma unroll
            for (int q=0;q<4;q++){
                const int row = lrow + q*32;
                const void* g = ah + (size_t)(rb+row)*512 + k0 + lc*8;
                const u32 sa = so + (u32)(row*128) + (u32)((lc ^ (row&7)) << 4);
                cpasync16(sa, g);
            }
        }
        CP_COMMIT();
    };

    issue(0); issue(1);
    for (int s=0; s<8; s++){
        if (s+1 < 8) { CP_WAIT1(); } else { CP_WAIT0(); }
        __syncthreads();
        if (s+2 < 8) issue(s+2);
        const u32 bufo = (u32)(s % 3) * 32768u;
        const u32 bA = sb+bufo, bB = sb+bufo+16384u;
        const int prA = (wm*64 + (lid&15)) * 128;
        const int prB0 = (wn*32 +      (lid&7) + ((lid>>4)<<3)) * 128;
        const int prB1 = (wn*32 + 16 + (lid&7) + ((lid>>4)<<3)) * 128;
#pragma unroll
        for (int st=0; st<4; st++){
            u32 Ah[4][4], Bh[4][2];
            const int xa = ((st*2 + (lid>>4))    ^ (lid&7)) << 4;
            const int xb = ((st*2 + ((lid>>3)&1)) ^ (lid&7)) << 4;
#pragma unroll
            for (int a=0;a<4;a++)
                ldsm4(Ah[a][0],Ah[a][1],Ah[a][2],Ah[a][3], bA + prA + a*2048 + xa);
            {
                u32 r0,r1,r2,r3;
                ldsm4(r0,r1,r2,r3, bB + prB0 + xb);
                Bh[0][0]=r0; Bh[0][1]=r1; Bh[1][0]=r2; Bh[1][1]=r3;
                ldsm4(r0,r1,r2,r3, bB + prB1 + xb);
                Bh[2][0]=r0; Bh[2][1]=r1; Bh[3][0]=r2; Bh[3][1]=r3;
            }
#pragma unroll
            for (int a=0;a<4;a++)
#pragma unroll
                for (int b=0;b<4;b++) mma16816(acc[a][b], Ah[a], Bh[b]);
        }
    }

    __syncthreads();
    float* Sm = (float*)dsm;
    float* P  = Sm + 128*129;
    const int tr = lid>>2, tc = (lid&3)*2;
#pragma unroll
    for (int a=0;a<4;a++)
#pragma unroll
        for (int hh=0; hh<2; hh++){
            const int rl = wm*64 + a*16 + tr + hh*8;
#pragma unroll
            for (int b=0;b<4;b++){
                const int cl = wn*32 + b*8 + tc;
                Sm[rl*129 + cl]     = acc[a][b][hh*2+0]*scale;
                Sm[rl*129 + cl + 1] = acc[a][b][hh*2+1]*scale;
            }
        }
    __syncthreads();

    const int rr = tid & 127, hf2 = tid >> 7;
    {
        float m = -1e30f;
        for (int c=0;c<64;c++) m = fmaxf(m, Sm[rr*129 + hf2*64 + c]);
        P[rr*2 + hf2] = m;
    }
    __syncthreads();
    if (tid < 128) atomicMax(&rmaxU[(size_t)z*TN + m0 + tid], fenc(fmaxf(P[tid*2], P[tid*2+1])));
    __syncthreads();
    {
        float m = -1e30f;
        for (int r2=0;r2<64;r2++) m = fmaxf(m, Sm[(hf2*64 + r2)*129 + rr]);
        P[rr*2 + hf2] = m;
    }
    __syncthreads();
    if (tid < 128) atomicMax(&rmaxU[(size_t)z*TN + n0 + tid], fenc(fmaxf(P[tid*2], P[tid*2+1])));

    const size_t obase = (size_t)z*TN*TN;
    {
        const int r = tid>>1, c0 = (tid&1)*64;
        float* op = att + obase + (size_t)(m0 + r)*TN + n0 + c0;
        const float* Sr = Sm + r*129 + c0;
#pragma unroll
        for (int it=0; it<16; it++){
            float4 w;
            w.x = Sr[it*4 + 0];
            w.y = Sr[it*4 + 1];
            w.z = Sr[it*4 + 2];
            w.w = Sr[it*4 + 3];
            *(float4*)(op + it*4) = w;
        }
    }
    if (i != j){
        const int c = tid>>1, r0 = (tid&1)*64;
        float* op = att + obase + (size_t)(n0 + c)*TN + m0 + r0;
#pragma unroll
        for (int it=0; it<16; it++){
            float4 w;
            w.x = Sm[(r0 + it*4 + 0)*129 + c];
            w.y = Sm[(r0 + it*4 + 1)*129 + c];
            w.z = Sm[(r0 + it*4 + 2)*129 + c];
            w.w = Sm[(r0 + it*4 + 3)*129 + c];
            *(float4*)(op + it*4) = w;
        }
    }
}

// ---------------- fused exp/rowsum/normalize ctx GEMM (2-stage, 2 CTAs/SM) ---
// M-tile 64, N=256, K=TN. Stage (40960 B): A 8K | B 32K, 2 stages.
#define CTX_STAGE 40960u
__global__ void __launch_bounds__(256,2) gemm_ctx_fused(
    const float* __restrict__ att,
    const __half* __restrict__ vh,
    const u32* __restrict__ rmaxU,
    __half* __restrict__ ch)
{
    extern __shared__ char dsm[];
    const int tid = threadIdx.x, wid = tid>>5, lid = tid&31;
    const int z = blockIdx.z;
    const int n0 = blockIdx.x*64;
    const size_t abase = (size_t)z*TN*TN;
    const __half* vhb = vh + (size_t)z*256*TN;
    const u32 sb = smem_u32(dsm);
    float* srow = (float*)(dsm + 2*CTX_STAGE);

    const int wm = wid>>2, wn = wid&3;
    const int lr = tid>>3, lc = tid&7;

    const float mx0 = fdec(rmaxU[(size_t)z*TN + n0 + lr]);
    const float mx1 = fdec(rmaxU[(size_t)z*TN + n0 + lr + 32]);
    const float* pA0 = att + abase + (size_t)(n0+lr)*TN + lc*8;
    const float* pA1 = pA0 + (size_t)32*TN;

    float acc[2][8][4];
#pragma unroll
    for (int i=0;i<2;i++)
#pragma unroll
        for (int j=0;j<8;j++)
#pragma unroll
            for (int q=0;q<4;q++) acc[i][j][q] = 0.f;
    float s0 = 0.f, s1 = 0.f;

    const int S = TN/64;   // 144
    __align__(16) float raf[16];
    auto ldgA = [&](int s){
        const int k0 = s<<6;
        *(uint4*)&raf[0]  = *(const uint4*)(pA0 + k0);
        *(uint4*)&raf[4]  = *(const uint4*)(pA0 + k0 + 4);
        *(uint4*)&raf[8]  = *(const uint4*)(pA1 + k0);
        *(uint4*)&raf[12] = *(const uint4*)(pA1 + k0 + 4);
    };
    auto issueB = [&](int s){
        const int k0 = s<<6;
        const u32 so = sb + (u32)(s&1)*CTX_STAGE + 8192u;
#pragma unroll
        for (int i=0;i<8;i++){
            const int row = lr + i*32;
            cpasync16(so + (u32)(row*128) + (u32)((lc ^ (row&7)) << 4),
                      vhb + (size_t)row*TN + k0 + lc*8);
        }
        CP_COMMIT();
    };
    auto exp8h = [&](const float* f, float mxv, float& ssum)->uint4{
        uint4 r;
        float e0, e1;
        e0 = __expf(f[0] - mxv); e1 = __expf(f[1] - mxv); ssum += e0 + e1;
        { __half2 h = __floats2half2_rn(e0, e1); r.x = *(u32*)&h; }
        e0 = __expf(f[2] - mxv); e1 = __expf(f[3] - mxv); ssum += e0 + e1;
        { __half2 h = __floats2half2_rn(e0, e1); r.y = *(u32*)&h; }
        e0 = __expf(f[4] - mxv); e1 = __expf(f[5] - mxv); ssum += e0 + e1;
        { __half2 h = __floats2half2_rn(e0, e1); r.z = *(u32*)&h; }
        e0 = __expf(f[6] - mxv); e1 = __expf(f[7] - mxv); ssum += e0 + e1;
        { __half2 h = __floats2half2_rn(e0, e1); r.w = *(u32*)&h; }
        return r;
    };
    const int aoff = lr*128 + ((lc ^ (lr&7)) << 4);

    // prologue: exp/STS stage 0 into buf0; B groups 0,1 in flight; raf preloaded for 1
    ldgA(0);
    {
        uint4 h0 = exp8h(&raf[0], mx0, s0);
        uint4 h1 = exp8h(&raf[8], mx1, s1);
        *(uint4*)(dsm + aoff)        = h0;
        *(uint4*)(dsm + aoff + 4096) = h1;
    }
    issueB(0);
    ldgA(1);
    issueB(1);

    for (int s=0; s<S; s++){
        if (s+1 < S) { CP_WAIT1(); } else { CP_WAIT0(); }
        __syncthreads();

        const u32 bufo = (u32)(s&1)*CTX_STAGE;
        const u32 bA = sb + bufo, bB = sb + bufo + 8192u;
#pragma unroll
        for (int st=0; st<4; st++){
            u32 Ah[2][4], Bh[8][2];
            const int xa = ((st*2 + (lid>>4))    ^ (lid&7)) << 4;
            const int xb = ((st*2 + ((lid>>3)&1)) ^ (lid&7)) << 4;
#pragma unroll
            for (int i=0;i<2;i++){
                const u32 pr = (u32)((wm*32 + i*16 + (lid&15)) * 128);
                ldsm4(Ah[i][0],Ah[i][1],Ah[i][2],Ah[i][3], bA + pr + xa);
            }
#pragma unroll
            for (int j2=0; j2<4; j2++){
                const u32 pr = (u32)((wn*64 + j2*16 + (lid&7) + ((lid>>4)<<3)) * 128);
                u32 r0,r1,r2,r3;
                ldsm4(r0,r1,r2,r3, bB + pr + xb);
                Bh[2*j2][0]=r0; Bh[2*j2][1]=r1; Bh[2*j2+1][0]=r2; Bh[2*j2+1][1]=r3;
            }
#pragma unroll
            for (int i=0;i<2;i++)
#pragma unroll
                for (int j=0;j<8;j++) mma16816(acc[i][j], Ah[i], Bh[j]);
        }

        // exp/STS for stage s+1 into the other buffer (A region was last read at s-1)
        if (s+1 < S){
            const int off2 = (int)((u32)((s+1)&1)*CTX_STAGE) + aoff;
            uint4 h0 = exp8h(&raf[0], mx0, s0);
            uint4 h1 = exp8h(&raf[8], mx1, s1);
            *(uint4*)(dsm + off2)        = h0;
            *(uint4*)(dsm + off2 + 4096) = h1;
        }
        __syncthreads();
        // refill the buffer just consumed (B via cp.async, raf for next exp)
        if (s+2 < S){
            issueB(s+2);
            ldgA(s+2);
        }
    }

#pragma unroll
    for (int o=1;o<8;o<<=1){
        s0 += __shfl_xor_sync(0xffffffffu, s0, o);
        s1 += __shfl_xor_sync(0xffffffffu, s1, o);
    }
    __syncthreads();
    if ((tid&7)==0){ srow[lr] = s0; srow[lr+32] = s1; }
    __syncthreads();

    const int tr = lid>>2, tc2 = (lid&3)*2;
#pragma unroll
    for (int i=0;i<2;i++){
#pragma unroll
        for (int hh=0; hh<2; hh++){
            const int rowl = wm*32 + i*16 + tr + hh*8;
            const float inv = 1.0f / srow[rowl];
            const int row = n0 + rowl;
            __half* oph = ch + (size_t)z*TN*256 + (size_t)row*256 + wn*64;
#pragma unroll
            for (int j=0;j<8;j++){
                const int col = j*8 + tc2;
                *(__half2*)(oph + col) =
                    __floats2half2_rn(acc[i][j][hh*2+0]*inv, acc[i][j][hh*2+1]*inv);
            }
        }
    }
}

// ---------------- merged prep: weights + rmax init + bcomb -------------------
__global__ void prep_all(
    const float* __restrict__ wk, const float* __restrict__ bk,
    const float* __restrict__ g1, const float* __restrict__ b1,
    const float* __restrict__ m1, const float* __restrict__ v1,
    const float* __restrict__ wv,
    const float* __restrict__ wW, const float* __restrict__ bW,
    const float* __restrict__ wo, const float* __restrict__ bo,
    const float* __restrict__ g2, const float* __restrict__ b2,
    const float* __restrict__ m2, const float* __restrict__ v2,
    __half* __restrict__ wkh, float* __restrict__ bkf,
    __half* __restrict__ wvh,
    __half* __restrict__ wWT,
    __half* __restrict__ woh, float* __restrict__ bcomb,
    u32* __restrict__ rmx)
{
    const int o = blockIdx.x, which = blockIdx.y, tid = threadIdx.x;
    if (which == 0){
        float s = g1[o] * rsqrtf(v1[o] + 1e-5f);
        for (int c = tid; c < 512; c += blockDim.x)
            wkh[o*512 + c] = __float2half_rn(wk[o*512 + c] * s);
        if (tid == 0) bkf[o] = bk[o]*s + b1[o] - m1[o]*s;
    } else if (which == 1){
        if (o < 256)
            for (int c = tid; c < 512; c += blockDim.x)
                wvh[o*512 + c] = __float2half_rn(wv[o*512 + c]);
    } else if (which == 2){
        for (int c = tid; c < 256; c += blockDim.x)
            wWT[c*512 + o] = __float2half_rn(wW[o*256 + c]);
    } else if (which == 3){
        float s = g2[o] * rsqrtf(v2[o] + 1e-5f);
        for (int c = tid; c < 512; c += blockDim.x)
            woh[o*512 + c] = __float2half_rn(wo[o*512 + c] * s);
    } else if (which == 4){
        const int idx = o*256 + tid;
        if (idx < NB*TN) rmx[idx] = 0u;
    } else {
        __shared__ float red[8];
        const float s = g2[o] * rsqrtf(v2[o] + 1e-5f);
        float acc = 0.f;
        for (int m = tid; m < 512; m += 256)
            acc += wo[o*512 + m] * bW[m];
#pragma unroll
        for (int off=16; off; off>>=1) acc += __shfl_xor_sync(0xffffffffu, acc, off);
        if ((tid&31)==0) red[tid>>5] = acc;
        __syncthreads();
        if (tid==0)
            bcomb[o] = (red[0]+red[1]+red[2]+red[3]+red[4]+red[5]+red[6]+red[7])*s
                       + bo[o]*s + b2[o] - m2[o]*s;
    }
}

__global__ void conv_x(const float* __restrict__ x, __half* __restrict__ xh)
{
    __shared__ float t[32][33];
    const int z = blockIdx.z;
    const float* xb = x + (size_t)z*512*TN;
    const int n0 = blockIdx.x*32, c0 = blockIdx.y*32;
    const int tx = threadIdx.x, ty = threadIdx.y;
#pragma unroll
    for (int i=0;i<4;i++)
        t[ty + i*8][tx] = xb[(size_t)(c0 + ty + i*8)*TN + n0 + tx];
    __syncthreads();
#pragma unroll
    for (int i=0;i<4;i++){
        int n = n0 + ty + i*8, c = c0 + tx;
        xh[((size_t)z*TN + n)*512 + c] = __float2half_rn(t[tx][ty + i*8]);
    }
}

// ---------------- launch ----------------------------------------------------
#define DSMEM_TC  98304
#define DSMEM_SYM 98304
#define DSMEM_CTX (2*40960 + 256)

extern "C" void kernel_launch(void* const* d_in, const int* in_sizes, int n_in,
                              void* d_out, int out_size)
{
    const float* x  = (const float*)d_in[0];
    const float* wk = (const float*)d_in[1];
    const float* bk = (const float*)d_in[2];
    const float* g1 = (const float*)d_in[3];
    const float* b1 = (const float*)d_in[4];
    const float* m1 = (const float*)d_in[5];
    const float* v1 = (const float*)d_in[6];
    const float* wv = (const float*)d_in[7];
    const float* bv = (const float*)d_in[8];
    const float* wW = (const float*)d_in[9];
    const float* bW = (const float*)d_in[10];
    const float* wo = (const float*)d_in[11];
    const float* bo = (const float*)d_in[12];
    const float* g2 = (const float*)d_in[13];
    const float* b2 = (const float*)d_in[14];
    const float* m2 = (const float*)d_in[15];
    const float* v2 = (const float*)d_in[16];
    float* out = (float*)d_out;

    cudaFuncSetAttribute(gemm_tc,        cudaFuncAttributeMaxDynamicSharedMemorySize, DSMEM_TC);
    cudaFuncSetAttribute(gemm_sym,       cudaFuncAttributeMaxDynamicSharedMemorySize, DSMEM_SYM);
    cudaFuncSetAttribute(gemm_ctx_fused, cudaFuncAttributeMaxDynamicSharedMemorySize, DSMEM_CTX);

    __half *xh,*kh,*vh,*ch,*wkh,*wvh,*wWT,*woh,*wcomb;
    float *att,*bkf,*bcomb; u32 *rmx;
    cudaGetSymbolAddress((void**)&xh, g_xh);
    cudaGetSymbolAddress((void**)&kh, g_kh);
    cudaGetSymbolAddress((void**)&vh, g_vh);
    cudaGetSymbolAddress((void**)&att, g_att);
    cudaGetSymbolAddress((void**)&ch, g_ch);
    cudaGetSymbolAddress((void**)&wkh, g_wkh);
    cudaGetSymbolAddress((void**)&wvh, g_wvh);
    cudaGetSymbolAddress((void**)&wWT, g_wWT);
    cudaGetSymbolAddress((void**)&woh, g_woh);
    cudaGetSymbolAddress((void**)&wcomb, g_wcomb);
    cudaGetSymbolAddress((void**)&bkf, g_bkf);
    cudaGetSymbolAddress((void**)&bcomb, g_bcomb);
    cudaGetSymbolAddress((void**)&rmx, g_rmax);

    // 0: all prep (weights, rmax init, bcomb)
    prep_all<<<dim3(512,6), 256>>>(wk, bk, g1, b1, m1, v1, wv, wW, bW, wo, bo,
                                   g2, b2, m2, v2,
                                   wkh, bkf, wvh, wWT, woh, bcomb, rmx);
    // 1: x transpose
    conv_x<<<dim3(TN/32, 16, NB), dim3(32,8)>>>(x, xh);
    // 2: k conv
    gemm_tc<<<dim3(72,4,NB), 256, DSMEM_TC>>>(xh, (size_t)TN*512, 512,
        wkh, 0, 512, 512, F_BCOL|F_RELU, bkf,
        kh, nullptr, (size_t)TN*512, 512);
    // 3: sim (profiled slot)
    gemm_sym<<<dim3(2628,1,NB), 256, DSMEM_SYM>>>(kh, 0.0441941738241592f, att, rmx);
    // 4: val conv
    gemm_tc<<<dim3(2,72,NB), 256, DSMEM_TC>>>(wvh, 0, 512,
        xh, (size_t)TN*512, 512, 512, F_BROW, bv,
        vh, nullptr, (size_t)256*TN, TN);
    // 5: ctx (2-stage, 2 CTAs/SM)
    gemm_ctx_fused<<<dim3(TN/64,1,NB), 256, DSMEM_CTX>>>(att, vh, rmx, ch);
    // 6: wcomb = woh · wWT
    gemm_tc<<<dim3(4,2,1), 256, DSMEM_TC>>>(woh, 0, 512,
        wWT, 0, 512, 512, 0, nullptr,
        wcomb, nullptr, 0, 256);
    // 7: out = relu(wcomb·ctx + bcomb), fp32
    gemm_tc<<<dim3(4,72,NB), 256, DSMEM_TC>>>(wcomb, 0, 256,
        ch, (size_t)TN*256, 256, 256, F_BROW|F_RELU|F_F32, bcomb,
        nullptr, out, (size_t)512*TN, TN);
}

// round 16
// speedup vs baseline: 1.3082x; 1.1900x over previous
#include <cuda_runtime.h>
#include <cuda_fp16.h>
#include <math.h>
#include <stdint.h>

#define TN 9216
#define NB 2
typedef unsigned int u32;
typedef unsigned long long u64;

#define F_RELU   1
#define F_BROW   2
#define F_BCOL   4
#define F_F32    16

// ---------------- scratch (static device arrays; no cudaMalloc allowed) ----
__device__ __half g_xh[(size_t)NB*TN*512];
__device__ __half g_kh[(size_t)NB*TN*512];
__device__ __half g_vh[(size_t)NB*256*TN];
__device__ float  g_att[(size_t)NB*TN*TN];      // 680 MB fp32 sim
__device__ __half g_ch[(size_t)NB*TN*256];
__device__ __half g_wkh[512*512];
__device__ __half g_wvh[256*512];
__device__ __half g_wWT[256*512];               // wW transposed
__device__ __half g_woh[512*512];
__device__ __half g_wcomb[512*256];             // wo_f · wW, fp16
__device__ float g_bkf[512], g_bcomb[512];
__device__ u32   g_rmax[NB*TN];

// ---------------- helpers ----------------------------------------------------
static __device__ __forceinline__ u32 smem_u32(const void* p){
    u32 a;
    asm("{ .reg .u64 t; cvta.to.shared.u64 t, %1; cvt.u32.u64 %0, t; }" : "=r"(a) : "l"(p));
    return a;
}
static __device__ __forceinline__ void cpasync16(u32 s, const void* g){
    asm volatile("cp.async.cg.shared.global [%0], [%1], 16;" :: "r"(s), "l"(g) : "memory");
}
#define CP_COMMIT() asm volatile("cp.async.commit_group;" ::: "memory")
#define CP_WAIT0()  asm volatile("cp.async.wait_group 0;" ::: "memory")
#define CP_WAIT1()  asm volatile("cp.async.wait_group 1;" ::: "memory")

static __device__ __forceinline__ void ldsm4(u32& r0, u32& r1, u32& r2, u32& r3, u32 a){
    asm volatile("ldmatrix.sync.aligned.m8n8.x4.shared.b16 {%0,%1,%2,%3}, [%4];"
                 : "=r"(r0), "=r"(r1), "=r"(r2), "=r"(r3) : "r"(a));
}
static __device__ __forceinline__ void mma16816(float* d, const u32* a, const u32* b){
    asm volatile("mma.sync.aligned.m16n8k16.row.col.f32.f16.f16.f32 "
                 "{%0,%1,%2,%3}, {%4,%5,%6,%7}, {%8,%9}, {%0,%1,%2,%3};"
                 : "+f"(d[0]), "+f"(d[1]), "+f"(d[2]), "+f"(d[3])
                 : "r"(a[0]), "r"(a[1]), "r"(a[2]), "r"(a[3]), "r"(b[0]), "r"(b[1]));
}
static __device__ __forceinline__ u32 fenc(float f){
    u32 u = __float_as_uint(f);
    return (u & 0x80000000u) ? ~u : (u | 0x80000000u);
}
static __device__ __forceinline__ float fdec(u32 u){
    return (u & 0x80000000u) ? __uint_as_float(u ^ 0x80000000u) : __uint_as_float(~u);
}

// ---------------- single-pass fp16 tensor GEMM (3-stage, 2 CTAs/SM) ----------
__global__ void __launch_bounds__(256,2) gemm_tc(
    const __half* __restrict__ a, size_t a_bs, int lda,
    const __half* __restrict__ b, size_t b_bs, int ldb,
    int K, int flags, const float* __restrict__ bias,
    __half* oh, float* of, size_t o_bs, int ldo)
{
    extern __shared__ char dsm[];
    const int tid = threadIdx.x, wid = tid>>5, lid = tid&31;
    const int m0 = blockIdx.x*128, n0 = blockIdx.y*128, z = blockIdx.z;
    a += (size_t)z*a_bs; b += (size_t)z*b_bs;
    const int wm = wid>>2, wn = wid&3;
    const u32 sb = smem_u32(dsm);
    const int lrow = tid>>3, lc = tid&7;

    float acc[4][4][4];
#pragma unroll
    for (int i=0;i<4;i++)
#pragma unroll
        for (int j=0;j<4;j++)
#pragma unroll
            for (int q=0;q<4;q++) acc[i][j][q] = 0.f;

    const int S = K >> 6;
    auto issue = [&](int s){
        const int k0 = s << 6;
        const u32 bufo = (u32)(s % 3) * 32768u;
#pragma unroll
        for (int arr=0; arr<2; arr++){
            const __half* gp = arr ? b : a;
            const int rb = arr ? n0 : m0;
            const int ld = arr ? ldb : lda;
            const u32 so = sb + bufo + arr*16384u;
#pragma unroll
            for (int i=0;i<4;i++){
                const int row = lrow + i*32;
                const void* g = gp + (size_t)(rb+row)*ld + k0 + lc*8;
                const u32 sa = so + (u32)(row*128) + (u32)((lc ^ (row&7)) << 4);
                cpasync16(sa, g);
            }
        }
        CP_COMMIT();
    };

    issue(0);
    issue(1);
    for (int s=0; s<S; s++){
        if (s+1 < S) { CP_WAIT1(); } else { CP_WAIT0(); }
        __syncthreads();
        if (s+2 < S) issue(s+2);
        const u32 bufo = (u32)(s % 3) * 32768u;
        const u32 bA = sb+bufo, bB = sb+bufo+16384u;
        const int prA = (wm*64 + (lid&15)) * 128;
        const int prB0 = (wn*32 +      (lid&7) + ((lid>>4)<<3)) * 128;
        const int prB1 = (wn*32 + 16 + (lid&7) + ((lid>>4)<<3)) * 128;
#pragma unroll
        for (int st=0; st<4; st++){
            u32 Ah[4][4], Bh[4][2];
            const int xa = ((st*2 + (lid>>4))    ^ (lid&7)) << 4;
            const int xb = ((st*2 + ((lid>>3)&1)) ^ (lid&7)) << 4;
#pragma unroll
            for (int i=0;i<4;i++)
                ldsm4(Ah[i][0],Ah[i][1],Ah[i][2],Ah[i][3], bA + prA + i*2048 + xa);
            {
                u32 r0,r1,r2,r3;
                ldsm4(r0,r1,r2,r3, bB + prB0 + xb);
                Bh[0][0]=r0; Bh[0][1]=r1; Bh[1][0]=r2; Bh[1][1]=r3;
                ldsm4(r0,r1,r2,r3, bB + prB1 + xb);
                Bh[2][0]=r0; Bh[2][1]=r1; Bh[3][0]=r2; Bh[3][1]=r3;
            }
#pragma unroll
            for (int i=0;i<4;i++)
#pragma unroll
                for (int j=0;j<4;j++) mma16816(acc[i][j], Ah[i], Bh[j]);
        }
    }

    const int tr = lid>>2, tc = (lid&3)*2;
    const int mBase = m0 + wm*64, nBase = n0 + wn*32;
#pragma unroll
    for (int i=0;i<4;i++){
#pragma unroll
        for (int hh=0; hh<2; hh++){
            const int row = mBase + i*16 + tr + hh*8;
            float brow = (flags & F_BROW) ? bias[row] : 0.f;
            if (flags & F_F32){
                float* op = of + (size_t)z*o_bs + (size_t)row*ldo;
#pragma unroll
                for (int j=0;j<4;j++){
                    const int n = nBase + j*8 + tc;
                    float v0 = acc[i][j][hh*2+0] + brow;
                    float v1 = acc[i][j][hh*2+1] + brow;
                    if (flags & F_BCOL){ v0 += bias[n]; v1 += bias[n+1]; }
                    if (flags & F_RELU){ v0 = fmaxf(v0,0.f); v1 = fmaxf(v1,0.f); }
                    float2 w; w.x = v0; w.y = v1;
                    *(float2*)(op + n) = w;
                }
            } else {
                __half* oph = oh + (size_t)z*o_bs + (size_t)row*ldo;
#pragma unroll
                for (int j=0;j<4;j++){
                    const int n = nBase + j*8 + tc;
                    float v0 = acc[i][j][hh*2+0] + brow;
                    float v1 = acc[i][j][hh*2+1] + brow;
                    if (flags & F_BCOL){ v0 += bias[n]; v1 += bias[n+1]; }
                    if (flags & F_RELU){ v0 = fmaxf(v0,0.f); v1 = fmaxf(v1,0.f); }
                    *(__half2*)(oph + n) = __floats2half2_rn(v0, v1);
                }
            }
        }
    }
}

// ---------------- symmetric sim GEMM: register-first epilogue ---------------
__global__ void __launch_bounds__(256,2) gemm_sym(
    const __half* __restrict__ kh,
    float scale, float* __restrict__ att, u32* __restrict__ rmaxU)
{
    extern __shared__ char dsm[];
    const int tid = threadIdx.x, wid = tid>>5, lid = tid&31;
    const int z = blockIdx.z;
    const int t = blockIdx.x;
    int i = (int)((145.0f - sqrtf(21025.0f - 8.0f*(float)t)) * 0.5f);
    while (i > 0 && i*72 - i*(i-1)/2 > t) i--;
    while ((i+1)*72 - (i+1)*i/2 <= t) i++;
    const int j = i + (t - (i*72 - i*(i-1)/2));
    const int m0 = i*128, n0 = j*128;

    const __half* ah = kh + (size_t)z*TN*512;
    const int wm = wid>>2, wn = wid&3;
    const u32 sb = smem_u32(dsm);
    const int lrow = tid>>3, lc = tid&7;

    float acc[4][4][4];
#pragma unroll
    for (int a=0;a<4;a++)
#pragma unroll
        for (int b=0;b<4;b++)
#pragma unroll
            for (int q=0;q<4;q++) acc[a][b][q] = 0.f;

    auto issue = [&](int s){
        const int k0 = s << 6;
        const u32 bufo = (u32)(s % 3) * 32768u;
#pragma unroll
        for (int arr=0; arr<2; arr++){
            const int rb = arr ? n0 : m0;
            const u32 so = sb + bufo + arr*16384u;
#pragma unroll
            for (int q=0;q<4;q++){
                const int row = lrow + q*32;
                const void* g = ah + (size_t)(rb+row)*512 + k0 + lc*8;
                const u32 sa = so + (u32)(row*128) + (u32)((lc ^ (row&7)) << 4);
                cpasync16(sa, g);
            }
        }
        CP_COMMIT();
    };

    issue(0); issue(1);
    for (int s=0; s<8; s++){
        if (s+1 < 8) { CP_WAIT1(); } else { CP_WAIT0(); }
        __syncthreads();
        if (s+2 < 8) issue(s+2);
        const u32 bufo = (u32)(s % 3) * 32768u;
        const u32 bA = sb+bufo, bB = sb+bufo+16384u;
        const int prA = (wm*64 + (lid&15)) * 128;
        const int prB0 = (wn*32 +      (lid&7) + ((lid>>4)<<3)) * 128;
        const int prB1 = (wn*32 + 16 + (lid&7) + ((lid>>4)<<3)) * 128;
#pragma unroll
        for (int st=0; st<4; st++){
            u32 Ah[4][4], Bh[4][2];
            const int xa = ((st*2 + (lid>>4))    ^ (lid&7)) << 4;
            const int xb = ((st*2 + ((lid>>3)&1)) ^ (lid&7)) << 4;
#pragma unroll
            for (int a=0;a<4;a++)
                ldsm4(Ah[a][0],Ah[a][1],Ah[a][2],Ah[a][3], bA + prA + a*2048 + xa);
            {
                u32 r0,r1,r2,r3;
                ldsm4(r0,r1,r2,r3, bB + prB0 + xb);
                Bh[0][0]=r0; Bh[0][1]=r1; Bh[1][0]=r2; Bh[1][1]=r3;
                ldsm4(r0,r1,r2,r3, bB + prB1 + xb);
                Bh[2][0]=r0; Bh[2][1]=r1; Bh[3][0]=r2; Bh[3][1]=r3;
            }
#pragma unroll
            for (int a=0;a<4;a++)
#pragma unroll
                for (int b=0;b<4;b++) mma16816(acc[a][b], Ah[a], Bh[b]);
        }
    }

    __syncthreads();   // mainloop done; smem reusable
    float* Sm = (float*)dsm;            // staging [128][129] (mirror only)
    float* P2 = Sm + 128*129;           // [128][4] per-warp row maxes
    float* P3 = P2 + 512;               // [128][2] per-warp col maxes
    const int tr = lid>>2, tc = (lid&3)*2;
    const size_t obase = (size_t)z*TN*TN;

    // --- row maxes from registers (reduce over lanes sharing a row: xor 1,2) ---
#pragma unroll
    for (int a=0;a<4;a++)
#pragma unroll
        for (int hh=0; hh<2; hh++){
            float rm = -1e30f;
#pragma unroll
            for (int b=0;b<4;b++)
                rm = fmaxf(rm, fmaxf(acc[a][b][hh*2], acc[a][b][hh*2+1]));
            rm = fmaxf(rm, __shfl_xor_sync(0xffffffffu, rm, 1));
            rm = fmaxf(rm, __shfl_xor_sync(0xffffffffu, rm, 2));
            if ((lid&3)==0)
                P2[(wm*64 + a*16 + tr + hh*8)*4 + wn] = rm;
        }
    // --- col maxes from registers (reduce over lanes sharing a col: xor 4,8,16) ---
#pragma unroll
    for (int b=0;b<4;b++)
#pragma unroll
        for (int p=0;p<2;p++){
            float cm = -1e30f;
#pragma unroll
            for (int a=0;a<4;a++)
                cm = fmaxf(cm, fmaxf(acc[a][b][p], acc[a][b][2+p]));
            cm = fmaxf(cm, __shfl_xor_sync(0xffffffffu, cm, 4));
            cm = fmaxf(cm, __shfl_xor_sync(0xffffffffu, cm, 8));
            cm = fmaxf(cm, __shfl_xor_sync(0xffffffffu, cm, 16));
            if (tr==0)
                P3[(wn*32 + b*8 + (lid&3)*2 + p)*2 + wm] = cm;
        }

    // --- staging STS for mirror (skip on diagonal tiles) ---
    if (i != j){
#pragma unroll
        for (int a=0;a<4;a++)
#pragma unroll
            for (int hh=0; hh<2; hh++){
                const int rl = wm*64 + a*16 + tr + hh*8;
#pragma unroll
                for (int b=0;b<4;b++){
                    const int cl = wn*32 + b*8 + tc;
                    Sm[rl*129 + cl]     = acc[a][b][hh*2+0]*scale;
                    Sm[rl*129 + cl + 1] = acc[a][b][hh*2+1]*scale;
                }
            }
    }

    // --- direct tile: write straight from registers (coalesced float2) ---
#pragma unroll
    for (int a=0;a<4;a++)
#pragma unroll
        for (int hh=0; hh<2; hh++){
            const int row = m0 + wm*64 + a*16 + tr + hh*8;
            float* op = att + obase + (size_t)row*TN + n0;
#pragma unroll
            for (int b=0;b<4;b++){
                const int cl = wn*32 + b*8 + tc;
                float2 w;
                w.x = acc[a][b][hh*2+0]*scale;
                w.y = acc[a][b][hh*2+1]*scale;
                *(float2*)(op + cl) = w;
            }
        }

    __syncthreads();
    // --- rmax atomics ---
    if (tid < 128){
        float rv = fmaxf(fmaxf(P2[tid*4+0], P2[tid*4+1]),
                         fmaxf(P2[tid*4+2], P2[tid*4+3])) * scale;
        atomicMax(&rmaxU[(size_t)z*TN + m0 + tid], fenc(rv));
        float cv = fmaxf(P3[tid*2+0], P3[tid*2+1]) * scale;
        atomicMax(&rmaxU[(size_t)z*TN + n0 + tid], fenc(cv));
    }
    // --- mirror: warp-per-row coalesced float4 stores ---
    if (i != j){
#pragma unroll
        for (int pass=0; pass<16; pass++){
            const int c = pass*8 + wid;
            float* op = att + obase + (size_t)(n0 + c)*TN + m0 + lid*4;
            float4 w;
            w.x = Sm[(lid*4 + 0)*129 + c];
            w.y = Sm[(lid*4 + 1)*129 + c];
            w.z = Sm[(lid*4 + 2)*129 + c];
            w.w = Sm[(lid*4 + 3)*129 + c];
            *(float4*)op = w;
        }
    }
}

// ---------------- fused exp/rowsum/normalize ctx GEMM (2-stage, 2 CTAs/SM) ---
#define CTX_STAGE 40960u
__global__ void __launch_bounds__(256,2) gemm_ctx_fused(
    const float* __restrict__ att,
    const __half* __restrict__ vh,
    const u32* __restrict__ rmaxU,
    __half* __restrict__ ch)
{
    extern __shared__ char dsm[];
    const int tid = threadIdx.x, wid = tid>>5, lid = tid&31;
    const int z = blockIdx.z;
    const int n0 = blockIdx.x*64;
    const size_t abase = (size_t)z*TN*TN;
    const __half* vhb = vh + (size_t)z*256*TN;
    const u32 sb = smem_u32(dsm);
    float* srow = (float*)(dsm + 2*CTX_STAGE);

    const int wm = wid>>2, wn = wid&3;
    const int lr = tid>>3, lc = tid&7;

    const float mx0 = fdec(rmaxU[(size_t)z*TN + n0 + lr]);
    const float mx1 = fdec(rmaxU[(size_t)z*TN + n0 + lr + 32]);
    const float* pA0 = att + abase + (size_t)(n0+lr)*TN + lc*8;
    const float* pA1 = pA0 + (size_t)32*TN;

    float acc[2][8][4];
#pragma unroll
    for (int i=0;i<2;i++)
#pragma unroll
        for (int j=0;j<8;j++)
#pragma unroll
            for (int q=0;q<4;q++) acc[i][j][q] = 0.f;
    float s0 = 0.f, s1 = 0.f;

    const int S = TN/64;   // 144
    __align__(16) float raf[16];
    auto ldgA = [&](int s){
        const int k0 = s<<6;
        *(uint4*)&raf[0]  = *(const uint4*)(pA0 + k0);
        *(uint4*)&raf[4]  = *(const uint4*)(pA0 + k0 + 4);
        *(uint4*)&raf[8]  = *(const uint4*)(pA1 + k0);
        *(uint4*)&raf[12] = *(const uint4*)(pA1 + k0 + 4);
    };
    auto issueB = [&](int s){
        const int k0 = s<<6;
        const u32 so = sb + (u32)(s&1)*CTX_STAGE + 8192u;
#pragma unroll
        for (int i=0;i<8;i++){
            const int row = lr + i*32;
            cpasync16(so + (u32)(row*128) + (u32)((lc ^ (row&7)) << 4),
                      vhb + (size_t)row*TN + k0 + lc*8);
        }
        CP_COMMIT();
    };
    auto exp8h = [&](const float* f, float mxv, float& ssum)->uint4{
        uint4 r;
        float e0, e1;
        e0 = __expf(f[0] - mxv); e1 = __expf(f[1] - mxv); ssum += e0 + e1;
        { __half2 h = __floats2half2_rn(e0, e1); r.x = *(u32*)&h; }
        e0 = __expf(f[2] - mxv); e1 = __expf(f[3] - mxv); ssum += e0 + e1;
        { __half2 h = __floats2half2_rn(e0, e1); r.y = *(u32*)&h; }
        e0 = __expf(f[4] - mxv); e1 = __expf(f[5] - mxv); ssum += e0 + e1;
        { __half2 h = __floats2half2_rn(e0, e1); r.z = *(u32*)&h; }
        e0 = __expf(f[6] - mxv); e1 = __expf(f[7] - mxv); ssum += e0 + e1;
        { __half2 h = __floats2half2_rn(e0, e1); r.w = *(u32*)&h; }
        return r;
    };
    const int aoff = lr*128 + ((lc ^ (lr&7)) << 4);

    ldgA(0);
    {
        uint4 h0 = exp8h(&raf[0], mx0, s0);
        uint4 h1 = exp8h(&raf[8], mx1, s1);
        *(uint4*)(dsm + aoff)        = h0;
        *(uint4*)(dsm + aoff + 4096) = h1;
    }
    issueB(0);
    ldgA(1);
    issueB(1);

    for (int s=0; s<S; s++){
        if (s+1 < S) { CP_WAIT1(); } else { CP_WAIT0(); }
        __syncthreads();

        const u32 bufo = (u32)(s&1)*CTX_STAGE;
        const u32 bA = sb + bufo, bB = sb + bufo + 8192u;
#pragma unroll
        for (int st=0; st<4; st++){
            u32 Ah[2][4], Bh[8][2];
            const int xa = ((st*2 + (lid>>4))    ^ (lid&7)) << 4;
            const int xb = ((st*2 + ((lid>>3)&1)) ^ (lid&7)) << 4;
#pragma unroll
            for (int i=0;i<2;i++){
                const u32 pr = (u32)((wm*32 + i*16 + (lid&15)) * 128);
                ldsm4(Ah[i][0],Ah[i][1],Ah[i][2],Ah[i][3], bA + pr + xa);
            }
#pragma unroll
            for (int j2=0; j2<4; j2++){
                const u32 pr = (u32)((wn*64 + j2*16 + (lid&7) + ((lid>>4)<<3)) * 128);
                u32 r0,r1,r2,r3;
                ldsm4(r0,r1,r2,r3, bB + pr + xb);
                Bh[2*j2][0]=r0; Bh[2*j2][1]=r1; Bh[2*j2+1][0]=r2; Bh[2*j2+1][1]=r3;
            }
#pragma unroll
            for (int i=0;i<2;i++)
#pragma unroll
                for (int j=0;j<8;j++) mma16816(acc[i][j], Ah[i], Bh[j]);
        }

        if (s+1 < S){
            const int off2 = (int)((u32)((s+1)&1)*CTX_STAGE) + aoff;
            uint4 h0 = exp8h(&raf[0], mx0, s0);
            uint4 h1 = exp8h(&raf[8], mx1, s1);
            *(uint4*)(dsm + off2)        = h0;
            *(uint4*)(dsm + off2 + 4096) = h1;
        }
        __syncthreads();
        if (s+2 < S){
            issueB(s+2);
            ldgA(s+2);
        }
    }

#pragma unroll
    for (int o=1;o<8;o<<=1){
        s0 += __shfl_xor_sync(0xffffffffu, s0, o);
        s1 += __shfl_xor_sync(0xffffffffu, s1, o);
    }
    __syncthreads();
    if ((tid&7)==0){ srow[lr] = s0; srow[lr+32] = s1; }
    __syncthreads();

    const int tr = lid>>2, tc2 = (lid&3)*2;
#pragma unroll
    for (int i=0;i<2;i++){
#pragma unroll
        for (int hh=0; hh<2; hh++){
            const int rowl = wm*32 + i*16 + tr + hh*8;
            const float inv = 1.0f / srow[rowl];
            const int row = n0 + rowl;
            __half* oph = ch + (size_t)z*TN*256 + (size_t)row*256 + wn*64;
#pragma unroll
            for (int j=0;j<8;j++){
                const int col = j*8 + tc2;
                *(__half2*)(oph + col) =
                    __floats2half2_rn(acc[i][j][hh*2+0]*inv, acc[i][j][hh*2+1]*inv);
            }
        }
    }
}

// ---------------- merged prep: weights + rmax init + bcomb -------------------
__global__ void prep_all(
    const float* __restrict__ wk, const float* __restrict__ bk,
    const float* __restrict__ g1, const float* __restrict__ b1,
    const float* __restrict__ m1, const float* __restrict__ v1,
    const float* __restrict__ wv,
    const float* __restrict__ wW, const float* __restrict__ bW,
    const float* __restrict__ wo, const float* __restrict__ bo,
    const float* __restrict__ g2, const float* __restrict__ b2,
    const float* __restrict__ m2, const float* __restrict__ v2,
    __half* __restrict__ wkh, float* __restrict__ bkf,
    __half* __restrict__ wvh,
    __half* __restrict__ wWT,
    __half* __restrict__ woh, float* __restrict__ bcomb,
    u32* __restrict__ rmx)
{
    const int o = blockIdx.x, which = blockIdx.y, tid = threadIdx.x;
    if (which == 0){
        float s = g1[o] * rsqrtf(v1[o] + 1e-5f);
        for (int c = tid; c < 512; c += blockDim.x)
            wkh[o*512 + c] = __float2half_rn(wk[o*512 + c] * s);
        if (tid == 0) bkf[o] = bk[o]*s + b1[o] - m1[o]*s;
    } else if (which == 1){
        if (o < 256)
            for (int c = tid; c < 512; c += blockDim.x)
                wvh[o*512 + c] = __float2half_rn(wv[o*512 + c]);
    } else if (which == 2){
        for (int c = tid; c < 256; c += blockDim.x)
            wWT[c*512 + o] = __float2half_rn(wW[o*256 + c]);
    } else if (which == 3){
        float s = g2[o] * rsqrtf(v2[o] + 1e-5f);
        for (int c = tid; c < 512; c += blockDim.x)
            woh[o*512 + c] = __float2half_rn(wo[o*512 + c] * s);
    } else if (which == 4){
        const int idx = o*256 + tid;
        if (idx < NB*TN) rmx[idx] = 0u;
    } else {
        __shared__ float red[8];
        const float s = g2[o] * rsqrtf(v2[o] + 1e-5f);
        float acc = 0.f;
        for (int m = tid; m < 512; m += 256)
            acc += wo[o*512 + m] * bW[m];
#pragma unroll
        for (int off=16; off; off>>=1) acc += __shfl_xor_sync(0xffffffffu, acc, off);
        if ((tid&31)==0) red[tid>>5] = acc;
        __syncthreads();
        if (tid==0)
            bcomb[o] = (red[0]+red[1]+red[2]+red[3]+red[4]+red[5]+red[6]+red[7])*s
                       + bo[o]*s + b2[o] - m2[o]*s;
    }
}

__global__ void conv_x(const float* __restrict__ x, __half* __restrict__ xh)
{
    __shared__ float t[32][33];
    const int z = blockIdx.z;
    const float* xb = x + (size_t)z*512*TN;
    const int n0 = blockIdx.x*32, c0 = blockIdx.y*32;
    const int tx = threadIdx.x, ty = threadIdx.y;
#pragma unroll
    for (int i=0;i<4;i++)
        t[ty + i*8][tx] = xb[(size_t)(c0 + ty + i*8)*TN + n0 + tx];
    __syncthreads();
#pragma unroll
    for (int i=0;i<4;i++){
        int n = n0 + ty + i*8, c = c0 + tx;
        xh[((size_t)z*TN + n)*512 + c] = __float2half_rn(t[tx][ty + i*8]);
    }
}

// ---------------- launch ----------------------------------------------------
#define DSMEM_TC  98304
#define DSMEM_SYM 98304
#define DSMEM_CTX (2*40960 + 256)

extern "C" void kernel_launch(void* const* d_in, const int* in_sizes, int n_in,
                              void* d_out, int out_size)
{
    const float* x  = (const float*)d_in[0];
    const float* wk = (const float*)d_in[1];
    const float* bk = (const float*)d_in[2];
    const float* g1 = (const float*)d_in[3];
    const float* b1 = (const float*)d_in[4];
    const float* m1 = (const float*)d_in[5];
    const float* v1 = (const float*)d_in[6];
    const float* wv = (const float*)d_in[7];
    const float* bv = (const float*)d_in[8];
    const float* wW = (const float*)d_in[9];
    const float* bW = (const float*)d_in[10];
    const float* wo = (const float*)d_in[11];
    const float* bo = (const float*)d_in[12];
    const float* g2 = (const float*)d_in[13];
    const float* b2 = (const float*)d_in[14];
    const float* m2 = (const float*)d_in[15];
    const float* v2 = (const float*)d_in[16];
    float* out = (float*)d_out;

    cudaFuncSetAttribute(gemm_tc,        cudaFuncAttributeMaxDynamicSharedMemorySize, DSMEM_TC);
    cudaFuncSetAttribute(gemm_sym,       cudaFuncAttributeMaxDynamicSharedMemorySize, DSMEM_SYM);
    cudaFuncSetAttribute(gemm_ctx_fused, cudaFuncAttributeMaxDynamicSharedMemorySize, DSMEM_CTX);

    __half *xh,*kh,*vh,*ch,*wkh,*wvh,*wWT,*woh,*wcomb;
    float *att,*bkf,*bcomb; u32 *rmx;
    cudaGetSymbolAddress((void**)&xh, g_xh);
    cudaGetSymbolAddress((void**)&kh, g_kh);
    cudaGetSymbolAddress((void**)&vh, g_vh);
    cudaGetSymbolAddress((void**)&att, g_att);
    cudaGetSymbolAddress((void**)&ch, g_ch);
    cudaGetSymbolAddress((void**)&wkh, g_wkh);
    cudaGetSymbolAddress((void**)&wvh, g_wvh);
    cudaGetSymbolAddress((void**)&wWT, g_wWT);
    cudaGetSymbolAddress((void**)&woh, g_woh);
    cudaGetSymbolAddress((void**)&wcomb, g_wcomb);
    cudaGetSymbolAddress((void**)&bkf, g_bkf);
    cudaGetSymbolAddress((void**)&bcomb, g_bcomb);
    cudaGetSymbolAddress((void**)&rmx, g_rmax);

    // 0: all prep (weights, rmax init, bcomb)
    prep_all<<<dim3(512,6), 256>>>(wk, bk, g1, b1, m1, v1, wv, wW, bW, wo, bo,
                                   g2, b2, m2, v2,
                                   wkh, bkf, wvh, wWT, woh, bcomb, rmx);
    // 1: x transpose
    conv_x<<<dim3(TN/32, 16, NB), dim3(32,8)>>>(x, xh);
    // 2: k conv
    gemm_tc<<<dim3(72,4,NB), 256, DSMEM_TC>>>(xh, (size_t)TN*512, 512,
        wkh, 0, 512, 512, F_BCOL|F_RELU, bkf,
        kh, nullptr, (size_t)TN*512, 512);
    // 3: sim (profiled slot)
    gemm_sym<<<dim3(2628,1,NB), 256, DSMEM_SYM>>>(kh, 0.0441941738241592f, att, rmx);
    // 4: val conv
    gemm_tc<<<dim3(2,72,NB), 256, DSMEM_TC>>>(wvh, 0, 512,
        xh, (size_t)TN*512, 512, 512, F_BROW, bv,
        vh, nullptr, (size_t)256*TN, TN);
    // 5: ctx (2-stage, 2 CTAs/SM)
    gemm_ctx_fused<<<dim3(TN/64,1,NB), 256, DSMEM_CTX>>>(att, vh, rmx, ch);
    // 6: wcomb = woh · wWT
    gemm_tc<<<dim3(4,2,1), 256, DSMEM_TC>>>(woh, 0, 512,
        wWT, 0, 512, 512, 0, nullptr,
        wcomb, nullptr, 0, 256);
    // 7: out = relu(wcomb·ctx + bcomb), fp32
    gemm_tc<<<dim3(4,72,NB), 256, DSMEM_TC>>>(wcomb, 0, 256,
        ch, (size_t)TN*256, 256, 256, F_BROW|F_RELU|F_F32, bcomb,
        nullptr, out, (size_t)512*TN, TN);
}

// round 17
// speedup vs baseline: 1.3962x; 1.0672x over previous
#include <cuda_runtime.h>
#include <cuda_fp16.h>
#include <math.h>
#include <stdint.h>

#define TN 9216
#define NB 2
typedef unsigned int u32;
typedef unsigned long long u64;

#define F_RELU   1
#define F_BROW   2
#define F_BCOL   4
#define F_F32    16

// ---------------- scratch (static device arrays; no cudaMalloc allowed) ----
__device__ __half g_xh[(size_t)NB*TN*512];
__device__ __half g_kh[(size_t)NB*TN*512];
__device__ __half g_vh[(size_t)NB*256*TN];
__device__ float  g_att[(size_t)NB*TN*TN];      // 680 MB fp32 sim
__device__ __half g_ch[(size_t)NB*TN*256];
__device__ __half g_wkh[512*512];
__device__ __half g_wvh[256*512];
__device__ __half g_wWT[256*512];               // wW transposed
__device__ __half g_woh[512*512];
__device__ __half g_wcomb[512*256];             // wo_f · wW, fp16
__device__ float g_bkf[512], g_bcomb[512];
__device__ u32   g_rmax[NB*TN];

// ---------------- helpers ----------------------------------------------------
static __device__ __forceinline__ u32 smem_u32(const void* p){
    u32 a;
    asm("{ .reg .u64 t; cvta.to.shared.u64 t, %1; cvt.u32.u64 %0, t; }" : "=r"(a) : "l"(p));
    return a;
}
static __device__ __forceinline__ void cpasync16(u32 s, const void* g){
    asm volatile("cp.async.cg.shared.global [%0], [%1], 16;" :: "r"(s), "l"(g) : "memory");
}
#define CP_COMMIT() asm volatile("cp.async.commit_group;" ::: "memory")
#define CP_WAIT0()  asm volatile("cp.async.wait_group 0;" ::: "memory")
#define CP_WAIT1()  asm volatile("cp.async.wait_group 1;" ::: "memory")

static __device__ __forceinline__ void ldsm4(u32& r0, u32& r1, u32& r2, u32& r3, u32 a){
    asm volatile("ldmatrix.sync.aligned.m8n8.x4.shared.b16 {%0,%1,%2,%3}, [%4];"
                 : "=r"(r0), "=r"(r1), "=r"(r2), "=r"(r3) : "r"(a));
}
static __device__ __forceinline__ void mma16816(float* d, const u32* a, const u32* b){
    asm volatile("mma.sync.aligned.m16n8k16.row.col.f32.f16.f16.f32 "
                 "{%0,%1,%2,%3}, {%4,%5,%6,%7}, {%8,%9}, {%0,%1,%2,%3};"
                 : "+f"(d[0]), "+f"(d[1]), "+f"(d[2]), "+f"(d[3])
                 : "r"(a[0]), "r"(a[1]), "r"(a[2]), "r"(a[3]), "r"(b[0]), "r"(b[1]));
}
static __device__ __forceinline__ u32 fenc(float f){
    u32 u = __float_as_uint(f);
    return (u & 0x80000000u) ? ~u : (u | 0x80000000u);
}
static __device__ __forceinline__ float fdec(u32 u){
    return (u & 0x80000000u) ? __uint_as_float(u ^ 0x80000000u) : __uint_as_float(~u);
}

// ---------------- single-pass fp16 tensor GEMM (3-stage, 2 CTAs/SM) ----------
__global__ void __launch_bounds__(256,2) gemm_tc(
    const __half* __restrict__ a, size_t a_bs, int lda,
    const __half* __restrict__ b, size_t b_bs, int ldb,
    int K, int flags, const float* __restrict__ bias,
    __half* oh, float* of, size_t o_bs, int ldo)
{
    extern __shared__ char dsm[];
    const int tid = threadIdx.x, wid = tid>>5, lid = tid&31;
    const int m0 = blockIdx.x*128, n0 = blockIdx.y*128, z = blockIdx.z;
    a += (size_t)z*a_bs; b += (size_t)z*b_bs;
    const int wm = wid>>2, wn = wid&3;
    const u32 sb = smem_u32(dsm);
    const int lrow = tid>>3, lc = tid&7;

    float acc[4][4][4];
#pragma unroll
    for (int i=0;i<4;i++)
#pragma unroll
        for (int j=0;j<4;j++)
#pragma unroll
            for (int q=0;q<4;q++) acc[i][j][q] = 0.f;

    const int S = K >> 6;
    auto issue = [&](int s){
        const int k0 = s << 6;
        const u32 bufo = (u32)(s % 3) * 32768u;
#pragma unroll
        for (int arr=0; arr<2; arr++){
            const __half* gp = arr ? b : a;
            const int rb = arr ? n0 : m0;
            const int ld = arr ? ldb : lda;
            const u32 so = sb + bufo + arr*16384u;
#pragma unroll
            for (int i=0;i<4;i++){
                const int row = lrow + i*32;
                const void* g = gp + (size_t)(rb+row)*ld + k0 + lc*8;
                const u32 sa = so + (u32)(row*128) + (u32)((lc ^ (row&7)) << 4);
                cpasync16(sa, g);
            }
        }
        CP_COMMIT();
    };

    issue(0);
    issue(1);
    for (int s=0; s<S; s++){
        if (s+1 < S) { CP_WAIT1(); } else { CP_WAIT0(); }
        __syncthreads();
        if (s+2 < S) issue(s+2);
        const u32 bufo = (u32)(s % 3) * 32768u;
        const u32 bA = sb+bufo, bB = sb+bufo+16384u;
        const int prA = (wm*64 + (lid&15)) * 128;
        const int prB0 = (wn*32 +      (lid&7) + ((lid>>4)<<3)) * 128;
        const int prB1 = (wn*32 + 16 + (lid&7) + ((lid>>4)<<3)) * 128;
#pragma unroll
        for (int st=0; st<4; st++){
            u32 Ah[4][4], Bh[4][2];
            const int xa = ((st*2 + (lid>>4))    ^ (lid&7)) << 4;
            const int xb = ((st*2 + ((lid>>3)&1)) ^ (lid&7)) << 4;
#pragma unroll
            for (int i=0;i<4;i++)
                ldsm4(Ah[i][0],Ah[i][1],Ah[i][2],Ah[i][3], bA + prA + i*2048 + xa);
            {
                u32 r0,r1,r2,r3;
                ldsm4(r0,r1,r2,r3, bB + prB0 + xb);
                Bh[0][0]=r0; Bh[0][1]=r1; Bh[1][0]=r2; Bh[1][1]=r3;
                ldsm4(r0,r1,r2,r3, bB + prB1 + xb);
                Bh[2][0]=r0; Bh[2][1]=r1; Bh[3][0]=r2; Bh[3][1]=r3;
            }
#pragma unroll
            for (int i=0;i<4;i++)
#pragma unroll
                for (int j=0;j<4;j++) mma16816(acc[i][j], Ah[i], Bh[j]);
        }
    }

    const int tr = lid>>2, tc = (lid&3)*2;
    const int mBase = m0 + wm*64, nBase = n0 + wn*32;
#pragma unroll
    for (int i=0;i<4;i++){
#pragma unroll
        for (int hh=0; hh<2; hh++){
            const int row = mBase + i*16 + tr + hh*8;
            float brow = (flags & F_BROW) ? bias[row] : 0.f;
            if (flags & F_F32){
                float* op = of + (size_t)z*o_bs + (size_t)row*ldo;
#pragma unroll
                for (int j=0;j<4;j++){
                    const int n = nBase + j*8 + tc;
                    float v0 = acc[i][j][hh*2+0] + brow;
                    float v1 = acc[i][j][hh*2+1] + brow;
                    if (flags & F_BCOL){ v0 += bias[n]; v1 += bias[n+1]; }
                    if (flags & F_RELU){ v0 = fmaxf(v0,0.f); v1 = fmaxf(v1,0.f); }
                    float2 w; w.x = v0; w.y = v1;
                    *(float2*)(op + n) = w;
                }
            } else {
                __half* oph = oh + (size_t)z*o_bs + (size_t)row*ldo;
#pragma unroll
                for (int j=0;j<4;j++){
                    const int n = nBase + j*8 + tc;
                    float v0 = acc[i][j][hh*2+0] + brow;
                    float v1 = acc[i][j][hh*2+1] + brow;
                    if (flags & F_BCOL){ v0 += bias[n]; v1 += bias[n+1]; }
                    if (flags & F_RELU){ v0 = fmaxf(v0,0.f); v1 = fmaxf(v1,0.f); }
                    *(__half2*)(oph + n) = __floats2half2_rn(v0, v1);
                }
            }
        }
    }
}

// ---------------- symmetric sim GEMM: register-first epilogue ---------------
// Mirror staging stored TRANSPOSED at stride 132 (16B-aligned columns,
// conflict-free STS) so mirror writes read contiguous LDS.128.
__global__ void __launch_bounds__(256,2) gemm_sym(
    const __half* __restrict__ kh,
    float scale, float* __restrict__ att, u32* __restrict__ rmaxU)
{
    extern __shared__ char dsm[];
    const int tid = threadIdx.x, wid = tid>>5, lid = tid&31;
    const int z = blockIdx.z;
    const int t = blockIdx.x;
    int i = (int)((145.0f - sqrtf(21025.0f - 8.0f*(float)t)) * 0.5f);
    while (i > 0 && i*72 - i*(i-1)/2 > t) i--;
    while ((i+1)*72 - (i+1)*i/2 <= t) i++;
    const int j = i + (t - (i*72 - i*(i-1)/2));
    const int m0 = i*128, n0 = j*128;

    const __half* ah = kh + (size_t)z*TN*512;
    const int wm = wid>>2, wn = wid&3;
    const u32 sb = smem_u32(dsm);
    const int lrow = tid>>3, lc = tid&7;

    float acc[4][4][4];
#pragma unroll
    for (int a=0;a<4;a++)
#pragma unroll
        for (int b=0;b<4;b++)
#pragma unroll
            for (int q=0;q<4;q++) acc[a][b][q] = 0.f;

    auto issue = [&](int s){
        const int k0 = s << 6;
        const u32 bufo = (u32)(s % 3) * 32768u;
#pragma unroll
        for (int arr=0; arr<2; arr++){
            const int rb = arr ? n0 : m0;
            const u32 so = sb + bufo + arr*16384u;
#pragma unroll
            for (int q=0;q<4;q++){
                const int row = lrow + q*32;
                const void* g = ah + (size_t)(rb+row)*512 + k0 + lc*8;
                const u32 sa = so + (u32)(row*128) + (u32)((lc ^ (row&7)) << 4);
                cpasync16(sa, g);
            }
        }
        CP_COMMIT();
    };

    issue(0); issue(1);
    for (int s=0; s<8; s++){
        if (s+1 < 8) { CP_WAIT1(); } else { CP_WAIT0(); }
        __syncthreads();
        if (s+2 < 8) issue(s+2);
        const u32 bufo = (u32)(s % 3) * 32768u;
        const u32 bA = sb+bufo, bB = sb+bufo+16384u;
        const int prA = (wm*64 + (lid&15)) * 128;
        const int prB0 = (wn*32 +      (lid&7) + ((lid>>4)<<3)) * 128;
        const int prB1 = (wn*32 + 16 + (lid&7) + ((lid>>4)<<3)) * 128;
#pragma unroll
        for (int st=0; st<4; st++){
            u32 Ah[4][4], Bh[4][2];
            const int xa = ((st*2 + (lid>>4))    ^ (lid&7)) << 4;
            const int xb = ((st*2 + ((lid>>3)&1)) ^ (lid&7)) << 4;
#pragma unroll
            for (int a=0;a<4;a++)
                ldsm4(Ah[a][0],Ah[a][1],Ah[a][2],Ah[a][3], bA + prA + a*2048 + xa);
            {
                u32 r0,r1,r2,r3;
                ldsm4(r0,r1,r2,r3, bB + prB0 + xb);
                Bh[0][0]=r0; Bh[0][1]=r1; Bh[1][0]=r2; Bh[1][1]=r3;
                ldsm4(r0,r1,r2,r3, bB + prB1 + xb);
                Bh[2][0]=r0; Bh[2][1]=r1; Bh[3][0]=r2; Bh[3][1]=r3;
            }
#pragma unroll
            for (int a=0;a<4;a++)
#pragma unroll
                for (int b=0;b<4;b++) mma16816(acc[a][b], Ah[a], Bh[b]);
        }
    }

    __syncthreads();   // mainloop done; smem reusable
    float* Sm = (float*)dsm;            // transposed staging [128 cols][132]
    float* P2 = Sm + 128*132;           // [128][4] per-warp row maxes
    float* P3 = P2 + 512;               // [128][2] per-warp col maxes
    const int tr = lid>>2, tc = (lid&3)*2;
    const size_t obase = (size_t)z*TN*TN;

    // --- row maxes from registers ---
#pragma unroll
    for (int a=0;a<4;a++)
#pragma unroll
        for (int hh=0; hh<2; hh++){
            float rm = -1e30f;
#pragma unroll
            for (int b=0;b<4;b++)
                rm = fmaxf(rm, fmaxf(acc[a][b][hh*2], acc[a][b][hh*2+1]));
            rm = fmaxf(rm, __shfl_xor_sync(0xffffffffu, rm, 1));
            rm = fmaxf(rm, __shfl_xor_sync(0xffffffffu, rm, 2));
            if ((lid&3)==0)
                P2[(wm*64 + a*16 + tr + hh*8)*4 + wn] = rm;
        }
    // --- col maxes from registers ---
#pragma unroll
    for (int b=0;b<4;b++)
#pragma unroll
        for (int p=0;p<2;p++){
            float cm = -1e30f;
#pragma unroll
            for (int a=0;a<4;a++)
                cm = fmaxf(cm, fmaxf(acc[a][b][p], acc[a][b][2+p]));
            cm = fmaxf(cm, __shfl_xor_sync(0xffffffffu, cm, 4));
            cm = fmaxf(cm, __shfl_xor_sync(0xffffffffu, cm, 8));
            cm = fmaxf(cm, __shfl_xor_sync(0xffffffffu, cm, 16));
            if (tr==0)
                P3[(wn*32 + b*8 + (lid&3)*2 + p)*2 + wm] = cm;
        }

    // --- transposed staging STS for mirror (skip on diagonal tiles) ---
    if (i != j){
#pragma unroll
        for (int a=0;a<4;a++)
#pragma unroll
            for (int hh=0; hh<2; hh++){
                const int rl = wm*64 + a*16 + tr + hh*8;
#pragma unroll
                for (int b=0;b<4;b++){
                    const int cl = wn*32 + b*8 + tc;
                    Sm[(cl  )*132 + rl] = acc[a][b][hh*2+0]*scale;
                    Sm[(cl+1)*132 + rl] = acc[a][b][hh*2+1]*scale;
                }
            }
    }

    // --- direct tile: write straight from registers (coalesced float2) ---
#pragma unroll
    for (int a=0;a<4;a++)
#pragma unroll
        for (int hh=0; hh<2; hh++){
            const int row = m0 + wm*64 + a*16 + tr + hh*8;
            float* op = att + obase + (size_t)row*TN + n0;
#pragma unroll
            for (int b=0;b<4;b++){
                const int cl = wn*32 + b*8 + tc;
                float2 w;
                w.x = acc[a][b][hh*2+0]*scale;
                w.y = acc[a][b][hh*2+1]*scale;
                *(float2*)(op + cl) = w;
            }
        }

    __syncthreads();
    // --- rmax atomics ---
    if (tid < 128){
        float rv = fmaxf(fmaxf(P2[tid*4+0], P2[tid*4+1]),
                         fmaxf(P2[tid*4+2], P2[tid*4+3])) * scale;
        atomicMax(&rmaxU[(size_t)z*TN + m0 + tid], fenc(rv));
        float cv = fmaxf(P3[tid*2+0], P3[tid*2+1]) * scale;
        atomicMax(&rmaxU[(size_t)z*TN + n0 + tid], fenc(cv));
    }
    // --- mirror: contiguous LDS.128 + coalesced float4 STG ---
    if (i != j){
#pragma unroll
        for (int pass=0; pass<16; pass++){
            const int c = pass*8 + wid;
            float* op = att + obase + (size_t)(n0 + c)*TN + m0 + lid*4;
            float4 w = *(const float4*)&Sm[c*132 + lid*4];
            *(float4*)op = w;
        }
    }
}

// ---------------- fused exp/rowsum/normalize ctx GEMM (2-stage, 2 CTAs/SM) ---
#define CTX_STAGE 40960u
__global__ void __launch_bounds__(256,2) gemm_ctx_fused(
    const float* __restrict__ att,
    const __half* __restrict__ vh,
    const u32* __restrict__ rmaxU,
    __half* __restrict__ ch)
{
    extern __shared__ char dsm[];
    const int tid = threadIdx.x, wid = tid>>5, lid = tid&31;
    const int z = blockIdx.z;
    const int n0 = blockIdx.x*64;
    const size_t abase = (size_t)z*TN*TN;
    const __half* vhb = vh + (size_t)z*256*TN;
    const u32 sb = smem_u32(dsm);
    float* srow = (float*)(dsm + 2*CTX_STAGE);

    const int wm = wid>>2, wn = wid&3;
    const int lr = tid>>3, lc = tid&7;

    const float mx0 = fdec(rmaxU[(size_t)z*TN + n0 + lr]);
    const float mx1 = fdec(rmaxU[(size_t)z*TN + n0 + lr + 32]);
    const float* pA0 = att + abase + (size_t)(n0+lr)*TN + lc*8;
    const float* pA1 = pA0 + (size_t)32*TN;

    float acc[2][8][4];
#pragma unroll
    for (int i=0;i<2;i++)
#pragma unroll
        for (int j=0;j<8;j++)
#pragma unroll
            for (int q=0;q<4;q++) acc[i][j][q] = 0.f;
    float s0 = 0.f, s1 = 0.f;

    const int S = TN/64;   // 144
    __align__(16) float raf[16];
    auto ldgA = [&](int s){
        const int k0 = s<<6;
        *(uint4*)&raf[0]  = *(const uint4*)(pA0 + k0);
        *(uint4*)&raf[4]  = *(const uint4*)(pA0 + k0 + 4);
        *(uint4*)&raf[8]  = *(const uint4*)(pA1 + k0);
        *(uint4*)&raf[12] = *(const uint4*)(pA1 + k0 + 4);
    };
    auto issueB = [&](int s){
        const int k0 = s<<6;
        const u32 so = sb + (u32)(s&1)*CTX_STAGE + 8192u;
#pragma unroll
        for (int i=0;i<8;i++){
            const int row = lr + i*32;
            cpasync16(so + (u32)(row*128) + (u32)((lc ^ (row&7)) << 4),
                      vhb + (size_t)row*TN + k0 + lc*8);
        }
        CP_COMMIT();
    };
    auto exp8h = [&](const float* f, float mxv, float& ssum)->uint4{
        uint4 r;
        float e0, e1;
        e0 = __expf(f[0] - mxv); e1 = __expf(f[1] - mxv); ssum += e0 + e1;
        { __half2 h = __floats2half2_rn(e0, e1); r.x = *(u32*)&h; }
        e0 = __expf(f[2] - mxv); e1 = __expf(f[3] - mxv); ssum += e0 + e1;
        { __half2 h = __floats2half2_rn(e0, e1); r.y = *(u32*)&h; }
        e0 = __expf(f[4] - mxv); e1 = __expf(f[5] - mxv); ssum += e0 + e1;
        { __half2 h = __floats2half2_rn(e0, e1); r.z = *(u32*)&h; }
        e0 = __expf(f[6] - mxv); e1 = __expf(f[7] - mxv); ssum += e0 + e1;
        { __half2 h = __floats2half2_rn(e0, e1); r.w = *(u32*)&h; }
        return r;
    };
    const int aoff = lr*128 + ((lc ^ (lr&7)) << 4);

    ldgA(0);
    {
        uint4 h0 = exp8h(&raf[0], mx0, s0);
        uint4 h1 = exp8h(&raf[8], mx1, s1);
        *(uint4*)(dsm + aoff)        = h0;
        *(uint4*)(dsm + aoff + 4096) = h1;
    }
    issueB(0);
    ldgA(1);
    issueB(1);

    for (int s=0; s<S; s++){
        if (s+1 < S) { CP_WAIT1(); } else { CP_WAIT0(); }
        __syncthreads();

        const u32 bufo = (u32)(s&1)*CTX_STAGE;
        const u32 bA = sb + bufo, bB = sb + bufo + 8192u;
#pragma unroll
        for (int st=0; st<4; st++){
            u32 Ah[2][4], Bh[8][2];
            const int xa = ((st*2 + (lid>>4))    ^ (lid&7)) << 4;
            const int xb = ((st*2 + ((lid>>3)&1)) ^ (lid&7)) << 4;
#pragma unroll
            for (int i=0;i<2;i++){
                const u32 pr = (u32)((wm*32 + i*16 + (lid&15)) * 128);
                ldsm4(Ah[i][0],Ah[i][1],Ah[i][2],Ah[i][3], bA + pr + xa);
            }
#pragma unroll
            for (int j2=0; j2<4; j2++){
                const u32 pr = (u32)((wn*64 + j2*16 + (lid&7) + ((lid>>4)<<3)) * 128);
                u32 r0,r1,r2,r3;
                ldsm4(r0,r1,r2,r3, bB + pr + xb);
                Bh[2*j2][0]=r0; Bh[2*j2][1]=r1; Bh[2*j2+1][0]=r2; Bh[2*j2+1][1]=r3;
            }
#pragma unroll
            for (int i=0;i<2;i++)
#pragma unroll
                for (int j=0;j<8;j++) mma16816(acc[i][j], Ah[i], Bh[j]);
        }

        if (s+1 < S){
            const int off2 = (int)((u32)((s+1)&1)*CTX_STAGE) + aoff;
            uint4 h0 = exp8h(&raf[0], mx0, s0);
            uint4 h1 = exp8h(&raf[8], mx1, s1);
            *(uint4*)(dsm + off2)        = h0;
            *(uint4*)(dsm + off2 + 4096) = h1;
        }
        __syncthreads();
        if (s+2 < S){
            issueB(s+2);
            ldgA(s+2);
        }
    }

#pragma unroll
    for (int o=1;o<8;o<<=1){
        s0 += __shfl_xor_sync(0xffffffffu, s0, o);
        s1 += __shfl_xor_sync(0xffffffffu, s1, o);
    }
    __syncthreads();
    if ((tid&7)==0){ srow[lr] = s0; srow[lr+32] = s1; }
    __syncthreads();

    const int tr = lid>>2, tc2 = (lid&3)*2;
#pragma unroll
    for (int i=0;i<2;i++){
#pragma unroll
        for (int hh=0; hh<2; hh++){
            const int rowl = wm*32 + i*16 + tr + hh*8;
            const float inv = 1.0f / srow[rowl];
            const int row = n0 + rowl;
            __half* oph = ch + (size_t)z*TN*256 + (size_t)row*256 + wn*64;
#pragma unroll
            for (int j=0;j<8;j++){
                const int col = j*8 + tc2;
                *(__half2*)(oph + col) =
                    __floats2half2_rn(acc[i][j][hh*2+0]*inv, acc[i][j][hh*2+1]*inv);
            }
        }
    }
}

// ---------------- merged prep: weights + rmax init + bcomb -------------------
__global__ void prep_all(
    const float* __restrict__ wk, const float* __restrict__ bk,
    const float* __restrict__ g1, const float* __restrict__ b1,
    const float* __restrict__ m1, const float* __restrict__ v1,
    const float* __restrict__ wv,
    const float* __restrict__ wW, const float* __restrict__ bW,
    const float* __restrict__ wo, const float* __restrict__ bo,
    const float* __restrict__ g2, const float* __restrict__ b2,
    const float* __restrict__ m2, const float* __restrict__ v2,
    __half* __restrict__ wkh, float* __restrict__ bkf,
    __half* __restrict__ wvh,
    __half* __restrict__ wWT,
    __half* __restrict__ woh, float* __restrict__ bcomb,
    u32* __restrict__ rmx)
{
    const int o = blockIdx.x, which = blockIdx.y, tid = threadIdx.x;
    if (which == 0){
        float s = g1[o] * rsqrtf(v1[o] + 1e-5f);
        for (int c = tid; c < 512; c += blockDim.x)
            wkh[o*512 + c] = __float2half_rn(wk[o*512 + c] * s);
        if (tid == 0) bkf[o] = bk[o]*s + b1[o] - m1[o]*s;
    } else if (which == 1){
        if (o < 256)
            for (int c = tid; c < 512; c += blockDim.x)
                wvh[o*512 + c] = __float2half_rn(wv[o*512 + c]);
    } else if (which == 2){
        for (int c = tid; c < 256; c += blockDim.x)
            wWT[c*512 + o] = __float2half_rn(wW[o*256 + c]);
    } else if (which == 3){
        float s = g2[o] * rsqrtf(v2[o] + 1e-5f);
        for (int c = tid; c < 512; c += blockDim.x)
            woh[o*512 + c] = __float2half_rn(wo[o*512 + c] * s);
    } else if (which == 4){
        const int idx = o*256 + tid;
        if (idx < NB*TN) rmx[idx] = 0u;
    } else {
        __shared__ float red[8];
        const float s = g2[o] * rsqrtf(v2[o] + 1e-5f);
        float acc = 0.f;
        for (int m = tid; m < 512; m += 256)
            acc += wo[o*512 + m] * bW[m];
#pragma unroll
        for (int off=16; off; off>>=1) acc += __shfl_xor_sync(0xffffffffu, acc, off);
        if ((tid&31)==0) red[tid>>5] = acc;
        __syncthreads();
        if (tid==0)
            bcomb[o] = (red[0]+red[1]+red[2]+red[3]+red[4]+red[5]+red[6]+red[7])*s
                       + bo[o]*s + b2[o] - m2[o]*s;
    }
}

__global__ void conv_x(const float* __restrict__ x, __half* __restrict__ xh)
{
    __shared__ float t[32][33];
    const int z = blockIdx.z;
    const float* xb = x + (size_t)z*512*TN;
    const int n0 = blockIdx.x*32, c0 = blockIdx.y*32;
    const int tx = threadIdx.x, ty = threadIdx.y;
#pragma unroll
    for (int i=0;i<4;i++)
        t[ty + i*8][tx] = xb[(size_t)(c0 + ty + i*8)*TN + n0 + tx];
    __syncthreads();
#pragma unroll
    for (int i=0;i<4;i++){
        int n = n0 + ty + i*8, c = c0 + tx;
        xh[((size_t)z*TN + n)*512 + c] = __float2half_rn(t[tx][ty + i*8]);
    }
}

// ---------------- launch ----------------------------------------------------
#define DSMEM_TC  98304
#define DSMEM_SYM 98304
#define DSMEM_CTX (2*40960 + 256)

extern "C" void kernel_launch(void* const* d_in, const int* in_sizes, int n_in,
                              void* d_out, int out_size)
{
    const float* x  = (const float*)d_in[0];
    const float* wk = (const float*)d_in[1];
    const float* bk = (const float*)d_in[2];
    const float* g1 = (const float*)d_in[3];
    const float* b1 = (const float*)d_in[4];
    const float* m1 = (const float*)d_in[5];
    const float* v1 = (const float*)d_in[6];
    const float* wv = (const float*)d_in[7];
    const float* bv = (const float*)d_in[8];
    const float* wW = (const float*)d_in[9];
    const float* bW = (const float*)d_in[10];
    const float* wo = (const float*)d_in[11];
    const float* bo = (const float*)d_in[12];
    const float* g2 = (const float*)d_in[13];
    const float* b2 = (const float*)d_in[14];
    const float* m2 = (const float*)d_in[15];
    const float* v2 = (const float*)d_in[16];
    float* out = (float*)d_out;

    cudaFuncSetAttribute(gemm_tc,        cudaFuncAttributeMaxDynamicSharedMemorySize, DSMEM_TC);
    cudaFuncSetAttribute(gemm_sym,       cudaFuncAttributeMaxDynamicSharedMemorySize, DSMEM_SYM);
    cudaFuncSetAttribute(gemm_ctx_fused, cudaFuncAttributeMaxDynamicSharedMemorySize, DSMEM_CTX);

    __half *xh,*kh,*vh,*ch,*wkh,*wvh,*wWT,*woh,*wcomb;
    float *att,*bkf,*bcomb; u32 *rmx;
    cudaGetSymbolAddress((void**)&xh, g_xh);
    cudaGetSymbolAddress((void**)&kh, g_kh);
    cudaGetSymbolAddress((void**)&vh, g_vh);
    cudaGetSymbolAddress((void**)&att, g_att);
    cudaGetSymbolAddress((void**)&ch, g_ch);
    cudaGetSymbolAddress((void**)&wkh, g_wkh);
    cudaGetSymbolAddress((void**)&wvh, g_wvh);
    cudaGetSymbolAddress((void**)&wWT, g_wWT);
    cudaGetSymbolAddress((void**)&woh, g_woh);
    cudaGetSymbolAddress((void**)&wcomb, g_wcomb);
    cudaGetSymbolAddress((void**)&bkf, g_bkf);
    cudaGetSymbolAddress((void**)&bcomb, g_bcomb);
    cudaGetSymbolAddress((void**)&rmx, g_rmax);

    // 0: all prep (weights, rmax init, bcomb)
    prep_all<<<dim3(512,6), 256>>>(wk, bk, g1, b1, m1, v1, wv, wW, bW, wo, bo,
                                   g2, b2, m2, v2,
                                   wkh, bkf, wvh, wWT, woh, bcomb, rmx);
    // 1: x transpose
    conv_x<<<dim3(TN/32, 16, NB), dim3(32,8)>>>(x, xh);
    // 2: k conv
    gemm_tc<<<dim3(72,4,NB), 256, DSMEM_TC>>>(xh, (size_t)TN*512, 512,
        wkh, 0, 512, 512, F_BCOL|F_RELU, bkf,
        kh, nullptr, (size_t)TN*512, 512);
    // 3: sim (profiled slot)
    gemm_sym<<<dim3(2628,1,NB), 256, DSMEM_SYM>>>(kh, 0.0441941738241592f, att, rmx);
    // 4: val conv
    gemm_tc<<<dim3(2,72,NB), 256, DSMEM_TC>>>(wvh, 0, 512,
        xh, (size_t)TN*512, 512, 512, F_BROW, bv,
        vh, nullptr, (size_t)256*TN, TN);
    // 5: ctx (2-stage, 2 CTAs/SM)
    gemm_ctx_fused<<<dim3(TN/64,1,NB), 256, DSMEM_CTX>>>(att, vh, rmx, ch);
    // 6: wcomb = woh · wWT
    gemm_tc<<<dim3(4,2,1), 256, DSMEM_TC>>>(woh, 0, 512,
        wWT, 0, 512, 512, 0, nullptr,
        wcomb, nullptr, 0, 256);
    // 7: out = relu(wcomb·ctx + bcomb), fp32
    gemm_tc<<<dim3(4,72,NB), 256, DSMEM_TC>>>(wcomb, 0, 256,
        ch, (size_t)TN*256, 256, 256, F_BROW|F_RELU|F_F32, bcomb,
        nullptr, out, (size_t)512*TN, TN);
}